// round 1
// baseline (speedup 1.0000x reference)
#include <cuda_runtime.h>
#include <cuda_bf16.h>
#include <cstdint>

// Problem constants
#define B_   2
#define S_   2048
#define E_   2048
#define NH_  32
#define NKV_ 8
#define HD_  64
#define GRP_ 4            // NH_/NKV_
#define MROWS (B_*S_)     // 4096

// ---------------- scratch (device globals; no allocation) ----------------
__device__ float g_q   [B_*S_*E_];          // q projection [B*S, 2048]
__device__ float g_k   [B_*S_*NKV_*HD_];    // k projection [B*S, 512]
__device__ float g_v   [B_*S_*NKV_*HD_];    // v projection [B*S, 512]
__device__ float g_qt  [B_*NH_*S_*HD_];     // q roped, [B,H,S,D]
__device__ float g_attn[B_*S_*E_];          // attention out, [B,S,E]

// ---------------- SGEMM: C[M,N] = A[M,K] * B[K,N], all row-major ----------
// 128x128 tile, BK=8, 256 threads, 8x8 per-thread microtile (2x2 of 4x4).
#define LDA_S 132
__global__ __launch_bounds__(256)
void sgemm128(const float* __restrict__ A, const float* __restrict__ Bm,
              float* __restrict__ C, int M, int N, int K)
{
    __shared__ float As[8 * LDA_S];   // [k][m], padded
    __shared__ float Bs[8 * LDA_S];   // [k][n], padded

    const int tid = threadIdx.x;
    const int m0 = blockIdx.y * 128;
    const int n0 = blockIdx.x * 128;

    const int a_row = tid >> 1;            // 0..127
    const int a_col = (tid & 1) * 4;       // 0 or 4
    const int b_row = tid >> 5;            // 0..7
    const int b_col = (tid & 31) * 4;      // 0..124

    const int tx = tid & 15;
    const int ty = tid >> 4;

    float acc[8][8];
    #pragma unroll
    for (int i = 0; i < 8; i++)
        #pragma unroll
        for (int j = 0; j < 8; j++) acc[i][j] = 0.f;

    const float* Aptr = A + (size_t)(m0 + a_row) * K + a_col;
    const float* Bptr = Bm + (size_t)b_row * N + n0 + b_col;

    for (int k0 = 0; k0 < K; k0 += 8) {
        float4 av = *(const float4*)(Aptr + k0);
        float4 bv = *(const float4*)(Bptr + (size_t)k0 * N);
        As[(a_col + 0) * LDA_S + a_row] = av.x;
        As[(a_col + 1) * LDA_S + a_row] = av.y;
        As[(a_col + 2) * LDA_S + a_row] = av.z;
        As[(a_col + 3) * LDA_S + a_row] = av.w;
        *(float4*)(Bs + b_row * LDA_S + b_col) = bv;
        __syncthreads();

        #pragma unroll
        for (int kk = 0; kk < 8; kk++) {
            float4 a0 = *(const float4*)(As + kk * LDA_S + ty * 4);
            float4 a1 = *(const float4*)(As + kk * LDA_S + 64 + ty * 4);
            float4 b0 = *(const float4*)(Bs + kk * LDA_S + tx * 4);
            float4 b1 = *(const float4*)(Bs + kk * LDA_S + 64 + tx * 4);
            float ra[8] = {a0.x,a0.y,a0.z,a0.w,a1.x,a1.y,a1.z,a1.w};
            float rb[8] = {b0.x,b0.y,b0.z,b0.w,b1.x,b1.y,b1.z,b1.w};
            #pragma unroll
            for (int i = 0; i < 8; i++)
                #pragma unroll
                for (int j = 0; j < 8; j++)
                    acc[i][j] += ra[i] * rb[j];
        }
        __syncthreads();
    }

    #pragma unroll
    for (int i = 0; i < 8; i++) {
        int r = m0 + ((i < 4) ? (ty * 4 + i) : (64 + ty * 4 + i - 4));
        float4 v1 = make_float4(acc[i][0], acc[i][1], acc[i][2], acc[i][3]);
        float4 v2 = make_float4(acc[i][4], acc[i][5], acc[i][6], acc[i][7]);
        *(float4*)(C + (size_t)r * N + n0 + tx * 4) = v1;
        *(float4*)(C + (size_t)r * N + n0 + 64 + tx * 4) = v2;
    }
}

// ---------------- RoPE + transpose kernels -------------------------------
// q: [B,S,H,D] -> roped -> [B,H,S,D]
__global__ void rope_q_kernel(const float* __restrict__ qp,
                              const float* __restrict__ cosT,
                              const float* __restrict__ sinT,
                              float* __restrict__ qt)
{
    int idx = blockIdx.x * blockDim.x + threadIdx.x;   // B*S*H*32
    if (idx >= B_ * S_ * NH_ * 32) return;
    int d = idx & 31;
    int h = (idx >> 5) & (NH_ - 1);
    int s = (idx >> 10) & (S_ - 1);
    int b = idx >> 21;
    const float* src = qp + ((size_t)(b * S_ + s)) * E_ + h * HD_;
    float x1 = src[d], x2 = src[d + 32];
    float c  = cosT[s * HD_ + d];
    float sn = sinT[s * HD_ + d];
    float* dst = qt + (((size_t)b * NH_ + h) * S_ + s) * HD_;
    dst[d]      = x1 * c - x2 * sn;
    dst[d + 32] = x2 * c + x1 * sn;
}

// k: [B,S,KV,D] -> roped -> [B,KV,S,D]  (this IS next_k)
__global__ void rope_k_kernel(const float* __restrict__ kp,
                              const float* __restrict__ cosT,
                              const float* __restrict__ sinT,
                              float* __restrict__ kt)
{
    int idx = blockIdx.x * blockDim.x + threadIdx.x;   // B*S*KV*32
    if (idx >= B_ * S_ * NKV_ * 32) return;
    int d = idx & 31;
    int h = (idx >> 5) & (NKV_ - 1);
    int s = (idx >> 8) & (S_ - 1);
    int b = idx >> 19;
    const float* src = kp + ((size_t)(b * S_ + s)) * (NKV_ * HD_) + h * HD_;
    float x1 = src[d], x2 = src[d + 32];
    float c  = cosT[s * HD_ + d];
    float sn = sinT[s * HD_ + d];
    float* dst = kt + (((size_t)b * NKV_ + h) * S_ + s) * HD_;
    dst[d]      = x1 * c - x2 * sn;
    dst[d + 32] = x2 * c + x1 * sn;
}

// v: [B,S,KV*D] -> [B,KV,S,D]  (this IS next_v), float4 granularity
__global__ void copy_v_kernel(const float* __restrict__ vp, float* __restrict__ vt)
{
    int idx = blockIdx.x * blockDim.x + threadIdx.x;   // B*S*128 float4s
    if (idx >= B_ * S_ * 128) return;
    int e4 = idx & 127;
    int s  = (idx >> 7) & (S_ - 1);
    int b  = idx >> 18;
    int e  = e4 * 4;
    int h  = e >> 6;
    int d  = e & 63;
    float4 v = *(const float4*)(vp + ((size_t)(b * S_ + s)) * (NKV_ * HD_) + e);
    *(float4*)(vt + (((size_t)b * NKV_ + h) * S_ + s) * HD_ + d) = v;
}

// ---------------- Flash attention (fp32, causal, GQA) ---------------------
// Block: (qtile of 64, head, batch). 256 threads, each owns 4x4 of the
// 64x64 score tile and 4x4 of the 64(rows)x64(D) O accumulator.
#define FLDS 68
__global__ __launch_bounds__(256)
void flash_attn(const float* __restrict__ Qt,   // [B,H,S,D] (pre-scaled? no: scale at load)
                const float* __restrict__ Kt,   // [B,KV,S,D]
                const float* __restrict__ Vt,   // [B,KV,S,D]
                float* __restrict__ Out)        // [B,S,E]
{
    extern __shared__ float sm[];
    float* Qs   = sm;                   // [64][FLDS]  (s, d), pre-scaled by 1/8
    float* Kst  = Qs  + 64 * FLDS;      // [64][FLDS]  (d, t)  <- transposed
    float* Vs   = Kst + 64 * FLDS;      // [64][FLDS]  (t, d)
    float* Ps   = Vs  + 64 * FLDS;      // [64][FLDS]  (s, t)
    float* red  = Ps  + 64 * FLDS;      // [64][17]
    float* row_m = red + 64 * 17;
    float* row_a = row_m + 64;
    float* row_l = row_a + 64;

    const int tid = threadIdx.x;
    const int tx = tid & 15, ty = tid >> 4;
    const int qtile = blockIdx.x;
    const int h = blockIdx.y;
    const int b = blockIdx.z;
    const int kv = h >> 2;       // GROUP = 4
    const int q0 = qtile * 64;
    const int r0 = ty * 4, c0 = tx * 4;

    const float* Qg = Qt + (((size_t)b * NH_ + h) * S_ + q0) * HD_;
    const float* Kb = Kt + ((size_t)b * NKV_ + kv) * S_ * HD_;
    const float* Vb = Vt + ((size_t)b * NKV_ + kv) * S_ * HD_;

    // load + pre-scale Q
    for (int l = tid; l < 64 * 16; l += 256) {
        int r = l >> 4, d4 = (l & 15) << 2;
        float4 v = *(const float4*)(Qg + r * 64 + d4);
        v.x *= 0.125f; v.y *= 0.125f; v.z *= 0.125f; v.w *= 0.125f;
        *(float4*)(Qs + r * FLDS + d4) = v;
    }
    if (tid < 64) { row_m[tid] = -1e30f; row_l[tid] = 0.f; }

    float accO[4][4];
    #pragma unroll
    for (int i = 0; i < 4; i++)
        #pragma unroll
        for (int j = 0; j < 4; j++) accO[i][j] = 0.f;

    for (int j = 0; j <= qtile; j++) {
        __syncthreads();   // protect Kst/Vs/Ps from previous iteration readers
        const float* Kg = Kb + (size_t)j * 64 * 64;
        const float* Vg = Vb + (size_t)j * 64 * 64;
        for (int l = tid; l < 64 * 16; l += 256) {
            int t = l >> 4, d4 = (l & 15) << 2;
            float4 kv4 = *(const float4*)(Kg + t * 64 + d4);
            Kst[(d4 + 0) * FLDS + t] = kv4.x;
            Kst[(d4 + 1) * FLDS + t] = kv4.y;
            Kst[(d4 + 2) * FLDS + t] = kv4.z;
            Kst[(d4 + 3) * FLDS + t] = kv4.w;
            float4 vv = *(const float4*)(Vg + t * 64 + d4);
            *(float4*)(Vs + t * FLDS + d4) = vv;
        }
        __syncthreads();

        // S = Q K^T  (Q pre-scaled)
        float Sc[4][4];
        #pragma unroll
        for (int i = 0; i < 4; i++)
            #pragma unroll
            for (int jj = 0; jj < 4; jj++) Sc[i][jj] = 0.f;

        #pragma unroll 16
        for (int kk = 0; kk < 64; kk++) {
            float4 kvv = *(const float4*)(Kst + kk * FLDS + c0);
            float qv0 = Qs[(r0 + 0) * FLDS + kk];
            float qv1 = Qs[(r0 + 1) * FLDS + kk];
            float qv2 = Qs[(r0 + 2) * FLDS + kk];
            float qv3 = Qs[(r0 + 3) * FLDS + kk];
            Sc[0][0] += qv0 * kvv.x; Sc[0][1] += qv0 * kvv.y; Sc[0][2] += qv0 * kvv.z; Sc[0][3] += qv0 * kvv.w;
            Sc[1][0] += qv1 * kvv.x; Sc[1][1] += qv1 * kvv.y; Sc[1][2] += qv1 * kvv.z; Sc[1][3] += qv1 * kvv.w;
            Sc[2][0] += qv2 * kvv.x; Sc[2][1] += qv2 * kvv.y; Sc[2][2] += qv2 * kvv.z; Sc[2][3] += qv2 * kvv.w;
            Sc[3][0] += qv3 * kvv.x; Sc[3][1] += qv3 * kvv.y; Sc[3][2] += qv3 * kvv.z; Sc[3][3] += qv3 * kvv.w;
        }

        if (j == qtile) {
            #pragma unroll
            for (int i = 0; i < 4; i++)
                #pragma unroll
                for (int jj = 0; jj < 4; jj++)
                    if (c0 + jj > r0 + i) Sc[i][jj] = -1e30f;
        }

        // row-max partials
        #pragma unroll
        for (int i = 0; i < 4; i++) {
            float pm = fmaxf(fmaxf(Sc[i][0], Sc[i][1]), fmaxf(Sc[i][2], Sc[i][3]));
            red[(r0 + i) * 17 + tx] = pm;
        }
        __syncthreads();
        if (tid < 64) {
            float mt = red[tid * 17];
            #pragma unroll
            for (int k = 1; k < 16; k++) mt = fmaxf(mt, red[tid * 17 + k]);
            float mo = row_m[tid];
            float mn = fmaxf(mo, mt);
            row_a[tid] = __expf(mo - mn);
            row_m[tid] = mn;
        }
        __syncthreads();

        // probs, O rescale, row-sum partials
        #pragma unroll
        for (int i = 0; i < 4; i++) {
            float al = row_a[r0 + i];
            float mi = row_m[r0 + i];
            float p0 = __expf(Sc[i][0] - mi);
            float p1 = __expf(Sc[i][1] - mi);
            float p2 = __expf(Sc[i][2] - mi);
            float p3 = __expf(Sc[i][3] - mi);
            accO[i][0] *= al; accO[i][1] *= al; accO[i][2] *= al; accO[i][3] *= al;
            float4 pv = make_float4(p0, p1, p2, p3);
            *(float4*)(Ps + (r0 + i) * FLDS + c0) = pv;
            red[(r0 + i) * 17 + tx] = p0 + p1 + p2 + p3;
        }
        __syncthreads();
        if (tid < 64) {
            float s = 0.f;
            #pragma unroll
            for (int k = 0; k < 16; k++) s += red[tid * 17 + k];
            row_l[tid] = row_l[tid] * row_a[tid] + s;
        }

        // O += P V
        #pragma unroll 16
        for (int kk = 0; kk < 64; kk++) {
            float4 vv = *(const float4*)(Vs + kk * FLDS + c0);
            float p0 = Ps[(r0 + 0) * FLDS + kk];
            float p1 = Ps[(r0 + 1) * FLDS + kk];
            float p2 = Ps[(r0 + 2) * FLDS + kk];
            float p3 = Ps[(r0 + 3) * FLDS + kk];
            accO[0][0] += p0 * vv.x; accO[0][1] += p0 * vv.y; accO[0][2] += p0 * vv.z; accO[0][3] += p0 * vv.w;
            accO[1][0] += p1 * vv.x; accO[1][1] += p1 * vv.y; accO[1][2] += p1 * vv.z; accO[1][3] += p1 * vv.w;
            accO[2][0] += p2 * vv.x; accO[2][1] += p2 * vv.y; accO[2][2] += p2 * vv.z; accO[2][3] += p2 * vv.w;
            accO[3][0] += p3 * vv.x; accO[3][1] += p3 * vv.y; accO[3][2] += p3 * vv.z; accO[3][3] += p3 * vv.w;
        }
    }

    __syncthreads();
    #pragma unroll
    for (int i = 0; i < 4; i++) {
        float inv = 1.f / row_l[r0 + i];
        int s_g = q0 + r0 + i;
        float4 o = make_float4(accO[i][0] * inv, accO[i][1] * inv,
                               accO[i][2] * inv, accO[i][3] * inv);
        *(float4*)(Out + ((size_t)(b * S_ + s_g)) * E_ + h * HD_ + c0) = o;
    }
}

// ---------------- launch ---------------------------------------------------
extern "C" void kernel_launch(void* const* d_in, const int* in_sizes, int n_in,
                              void* d_out, int out_size)
{
    const float* x    = (const float*)d_in[0];
    // d_in[1] = mask (causal; computed analytically, unused)
    const float* cosT = (const float*)d_in[2];
    const float* sinT = (const float*)d_in[3];
    const float* Wq   = (const float*)d_in[4];
    const float* Wk   = (const float*)d_in[5];
    const float* Wv   = (const float*)d_in[6];
    const float* Wo   = (const float*)d_in[7];

    float* out  = (float*)d_out;                       // [B,S,E]
    float* outK = out + (size_t)B_ * S_ * E_;          // [B,KV,S,D] = next_k
    float* outV = outK + (size_t)B_ * NKV_ * S_ * HD_; // [B,KV,S,D] = next_v

    float *gq, *gk, *gv, *gqt, *gattn;
    cudaGetSymbolAddress((void**)&gq,   g_q);
    cudaGetSymbolAddress((void**)&gk,   g_k);
    cudaGetSymbolAddress((void**)&gv,   g_v);
    cudaGetSymbolAddress((void**)&gqt,  g_qt);
    cudaGetSymbolAddress((void**)&gattn, g_attn);

    // projections
    sgemm128<<<dim3(E_ / 128, MROWS / 128), 256>>>(x, Wq, gq, MROWS, E_, E_);
    sgemm128<<<dim3((NKV_ * HD_) / 128, MROWS / 128), 256>>>(x, Wk, gk, MROWS, NKV_ * HD_, E_);
    sgemm128<<<dim3((NKV_ * HD_) / 128, MROWS / 128), 256>>>(x, Wv, gv, MROWS, NKV_ * HD_, E_);

    // rope + transposes (k/v go straight into d_out; they double as attention operands)
    {
        int tq = B_ * S_ * NH_ * 32;
        rope_q_kernel<<<(tq + 255) / 256, 256>>>(gq, cosT, sinT, gqt);
        int tk = B_ * S_ * NKV_ * 32;
        rope_k_kernel<<<(tk + 255) / 256, 256>>>(gk, cosT, sinT, outK);
        int tv = B_ * S_ * 128;
        copy_v_kernel<<<(tv + 255) / 256, 256>>>(gv, outV);
    }

    // flash attention
    {
        const int smem = (4 * 64 * FLDS + 64 * 17 + 3 * 64) * sizeof(float);
        cudaFuncSetAttribute(flash_attn, cudaFuncAttributeMaxDynamicSharedMemorySize, smem);
        dim3 grid(S_ / 64, NH_, B_);
        flash_attn<<<grid, 256, smem>>>(gqt, outK, outV, gattn);
    }

    // output projection
    sgemm128<<<dim3(E_ / 128, MROWS / 128), 256>>>(gattn, Wo, out, MROWS, E_, E_);
}

// round 2
// speedup vs baseline: 2.0527x; 2.0527x over previous
#include <cuda_runtime.h>
#include <cuda_bf16.h>
#include <cstdint>

// Problem constants
#define B_   2
#define S_   2048
#define E_   2048
#define NH_  32
#define NKV_ 8
#define HD_  64
#define GRP_ 4            // NH_/NKV_
#define MROWS (B_*S_)     // 4096

typedef __nv_bfloat16 bf16;

// ---------------- scratch (device globals; no allocation) ----------------
__device__ float g_q   [B_*S_*E_];          // q projection [B*S, 2048]
__device__ float g_k   [B_*S_*NKV_*HD_];    // k projection [B*S, 512]
__device__ float g_v   [B_*S_*NKV_*HD_];    // v projection [B*S, 512]
__device__ float g_qt  [B_*NH_*S_*HD_];     // q roped, [B,H,S,D]
__device__ float g_attn[B_*S_*E_];          // attention out, [B,S,E]

// bf16 split buffers
__device__ __align__(16) bf16 g_ahi[MROWS*E_];     // activation hi (x, then attn)
__device__ __align__(16) bf16 g_alo[MROWS*E_];     // activation lo
__device__ __align__(16) bf16 g_wqhi[E_*E_];       // Wq^T [N,K]
__device__ __align__(16) bf16 g_wqlo[E_*E_];
__device__ __align__(16) bf16 g_wkhi[(NKV_*HD_)*E_];
__device__ __align__(16) bf16 g_wklo[(NKV_*HD_)*E_];
__device__ __align__(16) bf16 g_wvhi[(NKV_*HD_)*E_];
__device__ __align__(16) bf16 g_wvlo[(NKV_*HD_)*E_];
__device__ __align__(16) bf16 g_wohi[E_*E_];
__device__ __align__(16) bf16 g_wolo[E_*E_];

// ---------------- split conversion kernels -------------------------------
// fp32 [n] -> hi/lo bf16 [n]
__global__ void split_kernel(const float* __restrict__ in,
                             bf16* __restrict__ hi, bf16* __restrict__ lo, int n)
{
    int i = blockIdx.x * blockDim.x + threadIdx.x;
    if (i >= n) return;
    float x = in[i];
    bf16 h = __float2bfloat16(x);
    hi[i] = h;
    lo[i] = __float2bfloat16(x - __bfloat162float(h));
}

// fp32 W [K,N] -> transposed hi/lo bf16 [N,K]
__global__ void splitT_kernel(const float* __restrict__ in,
                              bf16* __restrict__ hiT, bf16* __restrict__ loT,
                              int K, int N)
{
    __shared__ float t[32][33];
    int kb = blockIdx.y * 32, nb = blockIdx.x * 32;
    #pragma unroll
    for (int r = threadIdx.y; r < 32; r += 8)
        t[r][threadIdx.x] = in[(size_t)(kb + r) * N + nb + threadIdx.x];
    __syncthreads();
    #pragma unroll
    for (int r = threadIdx.y; r < 32; r += 8) {
        float x = t[threadIdx.x][r];
        bf16 h = __float2bfloat16(x);
        size_t o = (size_t)(nb + r) * K + kb + threadIdx.x;
        hiT[o] = h;
        loT[o] = __float2bfloat16(x - __bfloat162float(h));
    }
}

// ---------------- split-bf16 tensor-core GEMM ------------------------------
// C[M,N] (fp32) = sum_seg A_seg[M,K] * B_segT[N,K]^T
// segments: (Ahi,Bhi), (Ahi,Blo), (Alo,Bhi)
#define BM 128
#define BN 128
#define BKT 32
#define AST (BKT + 8)   // bf16 stride
#define BST (BKT + 8)

__global__ __launch_bounds__(256)
void gemm_bf16_split(const bf16* __restrict__ Ahi, const bf16* __restrict__ Alo,
                     const bf16* __restrict__ BhiT, const bf16* __restrict__ BloT,
                     float* __restrict__ C, int M, int N, int K)
{
    __shared__ __align__(16) bf16 As[BM * AST];
    __shared__ __align__(16) bf16 Bs[BN * BST];

    const int tid  = threadIdx.x;
    const int wid  = tid >> 5;
    const int lane = tid & 31;
    const int wm = (wid >> 2) * 64;     // 0,64
    const int wn = (wid & 3) * 32;      // 0..96
    const int m0 = blockIdx.y * BM;
    const int n0 = blockIdx.x * BN;

    const int lr = lane >> 2;           // 0..7
    const int lc = (lane & 3) * 2;      // 0,2,4,6

    float acc[4][4][4];
    #pragma unroll
    for (int i = 0; i < 4; i++)
        #pragma unroll
        for (int j = 0; j < 4; j++)
            #pragma unroll
            for (int r = 0; r < 4; r++) acc[i][j][r] = 0.f;

    const bf16* segA[3] = {Ahi, Ahi, Alo};
    const bf16* segB[3] = {BhiT, BloT, BhiT};

    const int KIT = K / BKT;
    const int NIT = 3 * KIT;

    // gmem load mapping: l in [0,512): row=l>>2, uint4 col = l&3
    const int l0 = tid, l1 = tid + 256;
    const int ar0 = l0 >> 2, au0 = (l0 & 3) * 8;
    const int ar1 = l1 >> 2, au1 = (l1 & 3) * 8;

    uint4 av0, av1, bv0, bv1;
    {
        const bf16* Ap = segA[0];
        const bf16* Bp = segB[0];
        av0 = *(const uint4*)(Ap + (size_t)(m0 + ar0) * K + au0);
        av1 = *(const uint4*)(Ap + (size_t)(m0 + ar1) * K + au1);
        bv0 = *(const uint4*)(Bp + (size_t)(n0 + ar0) * K + au0);
        bv1 = *(const uint4*)(Bp + (size_t)(n0 + ar1) * K + au1);
    }

    for (int it = 0; it < NIT; ++it) {
        __syncthreads();
        *(uint4*)(As + ar0 * AST + au0) = av0;
        *(uint4*)(As + ar1 * AST + au1) = av1;
        *(uint4*)(Bs + ar0 * BST + au0) = bv0;
        *(uint4*)(Bs + ar1 * BST + au1) = bv1;
        __syncthreads();

        if (it + 1 < NIT) {
            int nit = it + 1;
            int seg = nit / KIT;
            int k0  = (nit - seg * KIT) * BKT;
            const bf16* Ap = segA[seg];
            const bf16* Bp = segB[seg];
            av0 = *(const uint4*)(Ap + (size_t)(m0 + ar0) * K + k0 + au0);
            av1 = *(const uint4*)(Ap + (size_t)(m0 + ar1) * K + k0 + au1);
            bv0 = *(const uint4*)(Bp + (size_t)(n0 + ar0) * K + k0 + au0);
            bv1 = *(const uint4*)(Bp + (size_t)(n0 + ar1) * K + k0 + au1);
        }

        #pragma unroll
        for (int ks = 0; ks < 2; ks++) {
            const int kb = ks * 16;
            uint32_t af[4][4];
            #pragma unroll
            for (int mt = 0; mt < 4; mt++) {
                const bf16* base = As + (wm + mt * 16 + lr) * AST + kb + lc;
                af[mt][0] = *(const uint32_t*)(base);
                af[mt][1] = *(const uint32_t*)(base + 8 * AST);
                af[mt][2] = *(const uint32_t*)(base + 8);
                af[mt][3] = *(const uint32_t*)(base + 8 * AST + 8);
            }
            uint32_t bfg[4][2];
            #pragma unroll
            for (int nt = 0; nt < 4; nt++) {
                const bf16* base = Bs + (wn + nt * 8 + lr) * BST + kb + lc;
                bfg[nt][0] = *(const uint32_t*)(base);
                bfg[nt][1] = *(const uint32_t*)(base + 8);
            }
            #pragma unroll
            for (int mt = 0; mt < 4; mt++)
                #pragma unroll
                for (int nt = 0; nt < 4; nt++) {
                    asm volatile(
                        "mma.sync.aligned.m16n8k16.row.col.f32.bf16.bf16.f32 "
                        "{%0,%1,%2,%3}, {%4,%5,%6,%7}, {%8,%9}, {%0,%1,%2,%3};"
                        : "+f"(acc[mt][nt][0]), "+f"(acc[mt][nt][1]),
                          "+f"(acc[mt][nt][2]), "+f"(acc[mt][nt][3])
                        : "r"(af[mt][0]), "r"(af[mt][1]), "r"(af[mt][2]), "r"(af[mt][3]),
                          "r"(bfg[nt][0]), "r"(bfg[nt][1]));
                }
        }
    }

    // epilogue
    #pragma unroll
    for (int mt = 0; mt < 4; mt++) {
        #pragma unroll
        for (int nt = 0; nt < 4; nt++) {
            int r = m0 + wm + mt * 16 + lr;
            int c = n0 + wn + nt * 8 + lc;
            *(float2*)(C + (size_t)r * N + c) =
                make_float2(acc[mt][nt][0], acc[mt][nt][1]);
            *(float2*)(C + (size_t)(r + 8) * N + c) =
                make_float2(acc[mt][nt][2], acc[mt][nt][3]);
        }
    }
}

// ---------------- RoPE + transpose kernels -------------------------------
__global__ void rope_q_kernel(const float* __restrict__ qp,
                              const float* __restrict__ cosT,
                              const float* __restrict__ sinT,
                              float* __restrict__ qt)
{
    int idx = blockIdx.x * blockDim.x + threadIdx.x;
    if (idx >= B_ * S_ * NH_ * 32) return;
    int d = idx & 31;
    int h = (idx >> 5) & (NH_ - 1);
    int s = (idx >> 10) & (S_ - 1);
    int b = idx >> 21;
    const float* src = qp + ((size_t)(b * S_ + s)) * E_ + h * HD_;
    float x1 = src[d], x2 = src[d + 32];
    float c  = cosT[s * HD_ + d];
    float sn = sinT[s * HD_ + d];
    float* dst = qt + (((size_t)b * NH_ + h) * S_ + s) * HD_;
    dst[d]      = x1 * c - x2 * sn;
    dst[d + 32] = x2 * c + x1 * sn;
}

__global__ void rope_k_kernel(const float* __restrict__ kp,
                              const float* __restrict__ cosT,
                              const float* __restrict__ sinT,
                              float* __restrict__ kt)
{
    int idx = blockIdx.x * blockDim.x + threadIdx.x;
    if (idx >= B_ * S_ * NKV_ * 32) return;
    int d = idx & 31;
    int h = (idx >> 5) & (NKV_ - 1);
    int s = (idx >> 8) & (S_ - 1);
    int b = idx >> 19;
    const float* src = kp + ((size_t)(b * S_ + s)) * (NKV_ * HD_) + h * HD_;
    float x1 = src[d], x2 = src[d + 32];
    float c  = cosT[s * HD_ + d];
    float sn = sinT[s * HD_ + d];
    float* dst = kt + (((size_t)b * NKV_ + h) * S_ + s) * HD_;
    dst[d]      = x1 * c - x2 * sn;
    dst[d + 32] = x2 * c + x1 * sn;
}

__global__ void copy_v_kernel(const float* __restrict__ vp, float* __restrict__ vt)
{
    int idx = blockIdx.x * blockDim.x + threadIdx.x;
    if (idx >= B_ * S_ * 128) return;
    int e4 = idx & 127;
    int s  = (idx >> 7) & (S_ - 1);
    int b  = idx >> 18;
    int e  = e4 * 4;
    int h  = e >> 6;
    int d  = e & 63;
    float4 v = *(const float4*)(vp + ((size_t)(b * S_ + s)) * (NKV_ * HD_) + e);
    *(float4*)(vt + (((size_t)b * NKV_ + h) * S_ + s) * HD_ + d) = v;
}

// ---------------- Flash attention (fp32, causal, GQA) ---------------------
#define FLDS 68
__global__ __launch_bounds__(256)
void flash_attn(const float* __restrict__ Qt,
                const float* __restrict__ Kt,
                const float* __restrict__ Vt,
                float* __restrict__ Out)
{
    extern __shared__ float sm[];
    float* Qs   = sm;
    float* Kst  = Qs  + 64 * FLDS;
    float* Vs   = Kst + 64 * FLDS;
    float* Ps   = Vs  + 64 * FLDS;
    float* red  = Ps  + 64 * FLDS;
    float* row_m = red + 64 * 17;
    float* row_a = row_m + 64;
    float* row_l = row_a + 64;

    const int tid = threadIdx.x;
    const int tx = tid & 15, ty = tid >> 4;
    const int qtile = blockIdx.x;
    const int h = blockIdx.y;
    const int b = blockIdx.z;
    const int kv = h >> 2;
    const int q0 = qtile * 64;
    const int r0 = ty * 4, c0 = tx * 4;

    const float* Qg = Qt + (((size_t)b * NH_ + h) * S_ + q0) * HD_;
    const float* Kb = Kt + ((size_t)b * NKV_ + kv) * S_ * HD_;
    const float* Vb = Vt + ((size_t)b * NKV_ + kv) * S_ * HD_;

    for (int l = tid; l < 64 * 16; l += 256) {
        int r = l >> 4, d4 = (l & 15) << 2;
        float4 v = *(const float4*)(Qg + r * 64 + d4);
        v.x *= 0.125f; v.y *= 0.125f; v.z *= 0.125f; v.w *= 0.125f;
        *(float4*)(Qs + r * FLDS + d4) = v;
    }
    if (tid < 64) { row_m[tid] = -1e30f; row_l[tid] = 0.f; }

    float accO[4][4];
    #pragma unroll
    for (int i = 0; i < 4; i++)
        #pragma unroll
        for (int j = 0; j < 4; j++) accO[i][j] = 0.f;

    for (int j = 0; j <= qtile; j++) {
        __syncthreads();
        const float* Kg = Kb + (size_t)j * 64 * 64;
        const float* Vg = Vb + (size_t)j * 64 * 64;
        for (int l = tid; l < 64 * 16; l += 256) {
            int t = l >> 4, d4 = (l & 15) << 2;
            float4 kv4 = *(const float4*)(Kg + t * 64 + d4);
            Kst[(d4 + 0) * FLDS + t] = kv4.x;
            Kst[(d4 + 1) * FLDS + t] = kv4.y;
            Kst[(d4 + 2) * FLDS + t] = kv4.z;
            Kst[(d4 + 3) * FLDS + t] = kv4.w;
            float4 vv = *(const float4*)(Vg + t * 64 + d4);
            *(float4*)(Vs + t * FLDS + d4) = vv;
        }
        __syncthreads();

        float Sc[4][4];
        #pragma unroll
        for (int i = 0; i < 4; i++)
            #pragma unroll
            for (int jj = 0; jj < 4; jj++) Sc[i][jj] = 0.f;

        #pragma unroll 16
        for (int kk = 0; kk < 64; kk++) {
            float4 kvv = *(const float4*)(Kst + kk * FLDS + c0);
            float qv0 = Qs[(r0 + 0) * FLDS + kk];
            float qv1 = Qs[(r0 + 1) * FLDS + kk];
            float qv2 = Qs[(r0 + 2) * FLDS + kk];
            float qv3 = Qs[(r0 + 3) * FLDS + kk];
            Sc[0][0] += qv0 * kvv.x; Sc[0][1] += qv0 * kvv.y; Sc[0][2] += qv0 * kvv.z; Sc[0][3] += qv0 * kvv.w;
            Sc[1][0] += qv1 * kvv.x; Sc[1][1] += qv1 * kvv.y; Sc[1][2] += qv1 * kvv.z; Sc[1][3] += qv1 * kvv.w;
            Sc[2][0] += qv2 * kvv.x; Sc[2][1] += qv2 * kvv.y; Sc[2][2] += qv2 * kvv.z; Sc[2][3] += qv2 * kvv.w;
            Sc[3][0] += qv3 * kvv.x; Sc[3][1] += qv3 * kvv.y; Sc[3][2] += qv3 * kvv.z; Sc[3][3] += qv3 * kvv.w;
        }

        if (j == qtile) {
            #pragma unroll
            for (int i = 0; i < 4; i++)
                #pragma unroll
                for (int jj = 0; jj < 4; jj++)
                    if (c0 + jj > r0 + i) Sc[i][jj] = -1e30f;
        }

        #pragma unroll
        for (int i = 0; i < 4; i++) {
            float pm = fmaxf(fmaxf(Sc[i][0], Sc[i][1]), fmaxf(Sc[i][2], Sc[i][3]));
            red[(r0 + i) * 17 + tx] = pm;
        }
        __syncthreads();
        if (tid < 64) {
            float mt = red[tid * 17];
            #pragma unroll
            for (int k = 1; k < 16; k++) mt = fmaxf(mt, red[tid * 17 + k]);
            float mo = row_m[tid];
            float mn = fmaxf(mo, mt);
            row_a[tid] = __expf(mo - mn);
            row_m[tid] = mn;
        }
        __syncthreads();

        #pragma unroll
        for (int i = 0; i < 4; i++) {
            float al = row_a[r0 + i];
            float mi = row_m[r0 + i];
            float p0 = __expf(Sc[i][0] - mi);
            float p1 = __expf(Sc[i][1] - mi);
            float p2 = __expf(Sc[i][2] - mi);
            float p3 = __expf(Sc[i][3] - mi);
            accO[i][0] *= al; accO[i][1] *= al; accO[i][2] *= al; accO[i][3] *= al;
            float4 pv = make_float4(p0, p1, p2, p3);
            *(float4*)(Ps + (r0 + i) * FLDS + c0) = pv;
            red[(r0 + i) * 17 + tx] = p0 + p1 + p2 + p3;
        }
        __syncthreads();
        if (tid < 64) {
            float s = 0.f;
            #pragma unroll
            for (int k = 0; k < 16; k++) s += red[tid * 17 + k];
            row_l[tid] = row_l[tid] * row_a[tid] + s;
        }

        #pragma unroll 16
        for (int kk = 0; kk < 64; kk++) {
            float4 vv = *(const float4*)(Vs + kk * FLDS + c0);
            float p0 = Ps[(r0 + 0) * FLDS + kk];
            float p1 = Ps[(r0 + 1) * FLDS + kk];
            float p2 = Ps[(r0 + 2) * FLDS + kk];
            float p3 = Ps[(r0 + 3) * FLDS + kk];
            accO[0][0] += p0 * vv.x; accO[0][1] += p0 * vv.y; accO[0][2] += p0 * vv.z; accO[0][3] += p0 * vv.w;
            accO[1][0] += p1 * vv.x; accO[1][1] += p1 * vv.y; accO[1][2] += p1 * vv.z; accO[1][3] += p1 * vv.w;
            accO[2][0] += p2 * vv.x; accO[2][1] += p2 * vv.y; accO[2][2] += p2 * vv.z; accO[2][3] += p2 * vv.w;
            accO[3][0] += p3 * vv.x; accO[3][1] += p3 * vv.y; accO[3][2] += p3 * vv.z; accO[3][3] += p3 * vv.w;
        }
    }

    __syncthreads();
    #pragma unroll
    for (int i = 0; i < 4; i++) {
        float inv = 1.f / row_l[r0 + i];
        int s_g = q0 + r0 + i;
        float4 o = make_float4(accO[i][0] * inv, accO[i][1] * inv,
                               accO[i][2] * inv, accO[i][3] * inv);
        *(float4*)(Out + ((size_t)(b * S_ + s_g)) * E_ + h * HD_ + c0) = o;
    }
}

// ---------------- launch ---------------------------------------------------
extern "C" void kernel_launch(void* const* d_in, const int* in_sizes, int n_in,
                              void* d_out, int out_size)
{
    const float* x    = (const float*)d_in[0];
    const float* cosT = (const float*)d_in[2];
    const float* sinT = (const float*)d_in[3];
    const float* Wq   = (const float*)d_in[4];
    const float* Wk   = (const float*)d_in[5];
    const float* Wv   = (const float*)d_in[6];
    const float* Wo   = (const float*)d_in[7];

    float* out  = (float*)d_out;
    float* outK = out + (size_t)B_ * S_ * E_;
    float* outV = outK + (size_t)B_ * NKV_ * S_ * HD_;

    float *gq, *gk, *gv, *gqt, *gattn;
    bf16 *ahi, *alo, *wqhi, *wqlo, *wkhi, *wklo, *wvhi, *wvlo, *wohi, *wolo;
    cudaGetSymbolAddress((void**)&gq,    g_q);
    cudaGetSymbolAddress((void**)&gk,    g_k);
    cudaGetSymbolAddress((void**)&gv,    g_v);
    cudaGetSymbolAddress((void**)&gqt,   g_qt);
    cudaGetSymbolAddress((void**)&gattn, g_attn);
    cudaGetSymbolAddress((void**)&ahi,   g_ahi);
    cudaGetSymbolAddress((void**)&alo,   g_alo);
    cudaGetSymbolAddress((void**)&wqhi,  g_wqhi);
    cudaGetSymbolAddress((void**)&wqlo,  g_wqlo);
    cudaGetSymbolAddress((void**)&wkhi,  g_wkhi);
    cudaGetSymbolAddress((void**)&wklo,  g_wklo);
    cudaGetSymbolAddress((void**)&wvhi,  g_wvhi);
    cudaGetSymbolAddress((void**)&wvlo,  g_wvlo);
    cudaGetSymbolAddress((void**)&wohi,  g_wohi);
    cudaGetSymbolAddress((void**)&wolo,  g_wolo);

    // weight conversions (split + transpose to [N,K])
    {
        dim3 thr(32, 8);
        splitT_kernel<<<dim3(E_ / 32, E_ / 32), thr>>>(Wq, wqhi, wqlo, E_, E_);
        splitT_kernel<<<dim3((NKV_*HD_) / 32, E_ / 32), thr>>>(Wk, wkhi, wklo, E_, NKV_*HD_);
        splitT_kernel<<<dim3((NKV_*HD_) / 32, E_ / 32), thr>>>(Wv, wvhi, wvlo, E_, NKV_*HD_);
        splitT_kernel<<<dim3(E_ / 32, E_ / 32), thr>>>(Wo, wohi, wolo, E_, E_);
    }
    // activation conversion
    {
        int n = MROWS * E_;
        split_kernel<<<(n + 255) / 256, 256>>>(x, ahi, alo, n);
    }

    // projections (tensor core, split bf16)
    gemm_bf16_split<<<dim3(E_ / BN, MROWS / BM), 256>>>(ahi, alo, wqhi, wqlo, gq, MROWS, E_, E_);
    gemm_bf16_split<<<dim3((NKV_*HD_) / BN, MROWS / BM), 256>>>(ahi, alo, wkhi, wklo, gk, MROWS, NKV_*HD_, E_);
    gemm_bf16_split<<<dim3((NKV_*HD_) / BN, MROWS / BM), 256>>>(ahi, alo, wvhi, wvlo, gv, MROWS, NKV_*HD_, E_);

    // rope + transposes
    {
        int tq = B_ * S_ * NH_ * 32;
        rope_q_kernel<<<(tq + 255) / 256, 256>>>(gq, cosT, sinT, gqt);
        int tk = B_ * S_ * NKV_ * 32;
        rope_k_kernel<<<(tk + 255) / 256, 256>>>(gk, cosT, sinT, outK);
        int tv = B_ * S_ * 128;
        copy_v_kernel<<<(tv + 255) / 256, 256>>>(gv, outV);
    }

    // flash attention (fp32)
    {
        const int smem = (4 * 64 * FLDS + 64 * 17 + 3 * 64) * sizeof(float);
        cudaFuncSetAttribute(flash_attn, cudaFuncAttributeMaxDynamicSharedMemorySize, smem);
        dim3 grid(S_ / 64, NH_, B_);
        flash_attn<<<grid, 256, smem>>>(gqt, outK, outV, gattn);
    }

    // attention output conversion + output projection
    {
        int n = MROWS * E_;
        split_kernel<<<(n + 255) / 256, 256>>>(gattn, ahi, alo, n);
    }
    gemm_bf16_split<<<dim3(E_ / BN, MROWS / BM), 256>>>(ahi, alo, wohi, wolo, out, MROWS, E_, E_);
}

// round 3
// speedup vs baseline: 2.7360x; 1.3329x over previous
#include <cuda_runtime.h>
#include <cuda_bf16.h>
#include <cstdint>

// Problem constants
#define B_   2
#define S_   2048
#define E_   2048
#define NH_  32
#define NKV_ 8
#define HD_  64
#define GRP_ 4
#define MROWS (B_*S_)     // 4096

typedef __nv_bfloat16 bf16;

// ---------------- scratch (device globals; no allocation) ----------------
__device__ float g_q   [B_*S_*E_];          // q projection [B*S, 2048]
__device__ float g_k   [B_*S_*NKV_*HD_];    // k projection [B*S, 512]
__device__ float g_v   [B_*S_*NKV_*HD_];    // v projection [B*S, 512]

// bf16 split buffers
__device__ __align__(16) bf16 g_ahi[MROWS*E_];
__device__ __align__(16) bf16 g_alo[MROWS*E_];
__device__ __align__(16) bf16 g_wqhi[E_*E_];
__device__ __align__(16) bf16 g_wqlo[E_*E_];
__device__ __align__(16) bf16 g_wkhi[(NKV_*HD_)*E_];
__device__ __align__(16) bf16 g_wklo[(NKV_*HD_)*E_];
__device__ __align__(16) bf16 g_wvhi[(NKV_*HD_)*E_];
__device__ __align__(16) bf16 g_wvlo[(NKV_*HD_)*E_];
__device__ __align__(16) bf16 g_wohi[E_*E_];
__device__ __align__(16) bf16 g_wolo[E_*E_];

// attention operands (bf16 split)
__device__ __align__(16) bf16 g_qhi[B_*NH_*S_*HD_];   // [B,H,S,D], pre-scaled
__device__ __align__(16) bf16 g_qlo[B_*NH_*S_*HD_];
__device__ __align__(16) bf16 g_khi[B_*NKV_*S_*HD_];  // [B,KV,S,D]
__device__ __align__(16) bf16 g_klo[B_*NKV_*S_*HD_];
__device__ __align__(16) bf16 g_vthi[B_*NKV_*HD_*S_]; // [B,KV,D,S] (V^T)
__device__ __align__(16) bf16 g_vtlo[B_*NKV_*HD_*S_];

// ---------------- split conversion kernels -------------------------------
__global__ void split_kernel(const float* __restrict__ in,
                             bf16* __restrict__ hi, bf16* __restrict__ lo, int n)
{
    int i = blockIdx.x * blockDim.x + threadIdx.x;
    if (i >= n) return;
    float x = in[i];
    bf16 h = __float2bfloat16(x);
    hi[i] = h;
    lo[i] = __float2bfloat16(x - __bfloat162float(h));
}

// fp32 W [K,N] -> transposed hi/lo bf16 [N,K]
__global__ void splitT_kernel(const float* __restrict__ in,
                              bf16* __restrict__ hiT, bf16* __restrict__ loT,
                              int K, int N)
{
    __shared__ float t[32][33];
    int kb = blockIdx.y * 32, nb = blockIdx.x * 32;
    #pragma unroll
    for (int r = threadIdx.y; r < 32; r += 8)
        t[r][threadIdx.x] = in[(size_t)(kb + r) * N + nb + threadIdx.x];
    __syncthreads();
    #pragma unroll
    for (int r = threadIdx.y; r < 32; r += 8) {
        float x = t[threadIdx.x][r];
        bf16 h = __float2bfloat16(x);
        size_t o = (size_t)(nb + r) * K + kb + threadIdx.x;
        hiT[o] = h;
        loT[o] = __float2bfloat16(x - __bfloat162float(h));
    }
}

// ---------------- split-bf16 tensor-core GEMM (projections) ---------------
#define BM 128
#define BN 128
#define BKT 32
#define AST (BKT + 8)
#define BST (BKT + 8)

__global__ __launch_bounds__(256)
void gemm_bf16_split(const bf16* __restrict__ Ahi, const bf16* __restrict__ Alo,
                     const bf16* __restrict__ BhiT, const bf16* __restrict__ BloT,
                     float* __restrict__ C, int M, int N, int K)
{
    __shared__ __align__(16) bf16 As[BM * AST];
    __shared__ __align__(16) bf16 Bs[BN * BST];

    const int tid  = threadIdx.x;
    const int wid  = tid >> 5;
    const int lane = tid & 31;
    const int wm = (wid >> 2) * 64;
    const int wn = (wid & 3) * 32;
    const int m0 = blockIdx.y * BM;
    const int n0 = blockIdx.x * BN;

    const int lr = lane >> 2;
    const int lc = (lane & 3) * 2;

    float acc[4][4][4];
    #pragma unroll
    for (int i = 0; i < 4; i++)
        #pragma unroll
        for (int j = 0; j < 4; j++)
            #pragma unroll
            for (int r = 0; r < 4; r++) acc[i][j][r] = 0.f;

    const bf16* segA[3] = {Ahi, Ahi, Alo};
    const bf16* segB[3] = {BhiT, BloT, BhiT};

    const int KIT = K / BKT;
    const int NIT = 3 * KIT;

    const int l0 = tid, l1 = tid + 256;
    const int ar0 = l0 >> 2, au0 = (l0 & 3) * 8;
    const int ar1 = l1 >> 2, au1 = (l1 & 3) * 8;

    uint4 av0, av1, bv0, bv1;
    {
        const bf16* Ap = segA[0];
        const bf16* Bp = segB[0];
        av0 = *(const uint4*)(Ap + (size_t)(m0 + ar0) * K + au0);
        av1 = *(const uint4*)(Ap + (size_t)(m0 + ar1) * K + au1);
        bv0 = *(const uint4*)(Bp + (size_t)(n0 + ar0) * K + au0);
        bv1 = *(const uint4*)(Bp + (size_t)(n0 + ar1) * K + au1);
    }

    for (int it = 0; it < NIT; ++it) {
        __syncthreads();
        *(uint4*)(As + ar0 * AST + au0) = av0;
        *(uint4*)(As + ar1 * AST + au1) = av1;
        *(uint4*)(Bs + ar0 * BST + au0) = bv0;
        *(uint4*)(Bs + ar1 * BST + au1) = bv1;
        __syncthreads();

        if (it + 1 < NIT) {
            int nit = it + 1;
            int seg = nit / KIT;
            int k0  = (nit - seg * KIT) * BKT;
            const bf16* Ap = segA[seg];
            const bf16* Bp = segB[seg];
            av0 = *(const uint4*)(Ap + (size_t)(m0 + ar0) * K + k0 + au0);
            av1 = *(const uint4*)(Ap + (size_t)(m0 + ar1) * K + k0 + au1);
            bv0 = *(const uint4*)(Bp + (size_t)(n0 + ar0) * K + k0 + au0);
            bv1 = *(const uint4*)(Bp + (size_t)(n0 + ar1) * K + k0 + au1);
        }

        #pragma unroll
        for (int ks = 0; ks < 2; ks++) {
            const int kb = ks * 16;
            uint32_t af[4][4];
            #pragma unroll
            for (int mt = 0; mt < 4; mt++) {
                const bf16* base = As + (wm + mt * 16 + lr) * AST + kb + lc;
                af[mt][0] = *(const uint32_t*)(base);
                af[mt][1] = *(const uint32_t*)(base + 8 * AST);
                af[mt][2] = *(const uint32_t*)(base + 8);
                af[mt][3] = *(const uint32_t*)(base + 8 * AST + 8);
            }
            uint32_t bfg[4][2];
            #pragma unroll
            for (int nt = 0; nt < 4; nt++) {
                const bf16* base = Bs + (wn + nt * 8 + lr) * BST + kb + lc;
                bfg[nt][0] = *(const uint32_t*)(base);
                bfg[nt][1] = *(const uint32_t*)(base + 8);
            }
            #pragma unroll
            for (int mt = 0; mt < 4; mt++)
                #pragma unroll
                for (int nt = 0; nt < 4; nt++) {
                    asm volatile(
                        "mma.sync.aligned.m16n8k16.row.col.f32.bf16.bf16.f32 "
                        "{%0,%1,%2,%3}, {%4,%5,%6,%7}, {%8,%9}, {%0,%1,%2,%3};"
                        : "+f"(acc[mt][nt][0]), "+f"(acc[mt][nt][1]),
                          "+f"(acc[mt][nt][2]), "+f"(acc[mt][nt][3])
                        : "r"(af[mt][0]), "r"(af[mt][1]), "r"(af[mt][2]), "r"(af[mt][3]),
                          "r"(bfg[nt][0]), "r"(bfg[nt][1]));
                }
        }
    }

    #pragma unroll
    for (int mt = 0; mt < 4; mt++) {
        #pragma unroll
        for (int nt = 0; nt < 4; nt++) {
            int r = m0 + wm + mt * 16 + lr;
            int c = n0 + wn + nt * 8 + lc;
            *(float2*)(C + (size_t)r * N + c) =
                make_float2(acc[mt][nt][0], acc[mt][nt][1]);
            *(float2*)(C + (size_t)(r + 8) * N + c) =
                make_float2(acc[mt][nt][2], acc[mt][nt][3]);
        }
    }
}

// ---------------- RoPE + transpose kernels -------------------------------
// q: [B,S,H,D] -> roped*0.125 -> bf16 hi/lo [B,H,S,D]
__global__ void rope_q_kernel(const float* __restrict__ qp,
                              const float* __restrict__ cosT,
                              const float* __restrict__ sinT,
                              bf16* __restrict__ qhi, bf16* __restrict__ qlo)
{
    int idx = blockIdx.x * blockDim.x + threadIdx.x;
    if (idx >= B_ * S_ * NH_ * 32) return;
    int d = idx & 31;
    int h = (idx >> 5) & (NH_ - 1);
    int s = (idx >> 10) & (S_ - 1);
    int b = idx >> 21;
    const float* src = qp + ((size_t)(b * S_ + s)) * E_ + h * HD_;
    float x1 = src[d], x2 = src[d + 32];
    float c  = cosT[s * HD_ + d];
    float sn = sinT[s * HD_ + d];
    float y1 = (x1 * c - x2 * sn) * 0.125f;
    float y2 = (x2 * c + x1 * sn) * 0.125f;
    size_t o = (((size_t)b * NH_ + h) * S_ + s) * HD_;
    bf16 h1 = __float2bfloat16(y1);
    bf16 h2 = __float2bfloat16(y2);
    qhi[o + d]      = h1;
    qhi[o + d + 32] = h2;
    qlo[o + d]      = __float2bfloat16(y1 - __bfloat162float(h1));
    qlo[o + d + 32] = __float2bfloat16(y2 - __bfloat162float(h2));
}

// k: [B,S,KV,D] -> roped -> fp32 next_k [B,KV,S,D] + bf16 hi/lo
__global__ void rope_k_kernel(const float* __restrict__ kp,
                              const float* __restrict__ cosT,
                              const float* __restrict__ sinT,
                              float* __restrict__ kt,
                              bf16* __restrict__ khi, bf16* __restrict__ klo)
{
    int idx = blockIdx.x * blockDim.x + threadIdx.x;
    if (idx >= B_ * S_ * NKV_ * 32) return;
    int d = idx & 31;
    int h = (idx >> 5) & (NKV_ - 1);
    int s = (idx >> 8) & (S_ - 1);
    int b = idx >> 19;
    const float* src = kp + ((size_t)(b * S_ + s)) * (NKV_ * HD_) + h * HD_;
    float x1 = src[d], x2 = src[d + 32];
    float c  = cosT[s * HD_ + d];
    float sn = sinT[s * HD_ + d];
    float y1 = x1 * c - x2 * sn;
    float y2 = x2 * c + x1 * sn;
    size_t o = (((size_t)b * NKV_ + h) * S_ + s) * HD_;
    kt[o + d]      = y1;
    kt[o + d + 32] = y2;
    bf16 h1 = __float2bfloat16(y1);
    bf16 h2 = __float2bfloat16(y2);
    khi[o + d]      = h1;
    khi[o + d + 32] = h2;
    klo[o + d]      = __float2bfloat16(y1 - __bfloat162float(h1));
    klo[o + d + 32] = __float2bfloat16(y2 - __bfloat162float(h2));
}

// v: [B,S,KV*D] -> fp32 next_v [B,KV,S,D]
__global__ void copy_v_kernel(const float* __restrict__ vp, float* __restrict__ vt)
{
    int idx = blockIdx.x * blockDim.x + threadIdx.x;
    if (idx >= B_ * S_ * 128) return;
    int e4 = idx & 127;
    int s  = (idx >> 7) & (S_ - 1);
    int b  = idx >> 18;
    int e  = e4 * 4;
    int h  = e >> 6;
    int d  = e & 63;
    float4 v = *(const float4*)(vp + ((size_t)(b * S_ + s)) * (NKV_ * HD_) + e);
    *(float4*)(vt + (((size_t)b * NKV_ + h) * S_ + s) * HD_ + d) = v;
}

// v: [B,S,KV*D] -> V^T bf16 hi/lo [B,KV,D,S]  (tiled transpose)
__global__ void vT_split_kernel(const float* __restrict__ vp,
                                bf16* __restrict__ vthi, bf16* __restrict__ vtlo)
{
    __shared__ float t[64][33];   // [d][s] tile (s-tile of 32)
    int s0 = blockIdx.x * 32;
    int kvb = blockIdx.y;           // b*NKV + kv
    int b  = kvb / NKV_;
    int kv = kvb % NKV_;
    int tid = threadIdx.x;          // 256
    // read 32 s-rows x 64 d, coalesced
    for (int l = tid; l < 32 * 16; l += 256) {
        int s = l >> 4, d4 = (l & 15) * 4;
        float4 v = *(const float4*)(vp + ((size_t)(b * S_ + s0 + s)) * (NKV_ * HD_) + kv * HD_ + d4);
        t[d4 + 0][s] = v.x;
        t[d4 + 1][s] = v.y;
        t[d4 + 2][s] = v.z;
        t[d4 + 3][s] = v.w;
    }
    __syncthreads();
    // write 64 d-rows x 32 s, coalesced
    for (int l = tid; l < 64 * 32; l += 256) {
        int d = l >> 5, s = l & 31;
        float x = t[d][s];
        bf16 h = __float2bfloat16(x);
        size_t o = (((size_t)b * NKV_ + kv) * HD_ + d) * S_ + s0 + s;
        vthi[o] = h;
        vtlo[o] = __float2bfloat16(x - __bfloat162float(h));
    }
}

// ---------------- Flash attention (tensor core, split-bf16) ---------------
// 128 q-rows x 64 kv-cols per iter; 8 warps, each owns 16 q-rows.
#define KSTR 72
__global__ __launch_bounds__(256)
void flash_mma(const bf16* __restrict__ qhi, const bf16* __restrict__ qlo,
               const bf16* __restrict__ khi, const bf16* __restrict__ klo,
               const bf16* __restrict__ vthi, const bf16* __restrict__ vtlo,
               bf16* __restrict__ ohi, bf16* __restrict__ olo)
{
    __shared__ __align__(16) bf16 Kh[64 * KSTR];
    __shared__ __align__(16) bf16 Kl[64 * KSTR];
    __shared__ __align__(16) bf16 Vh[64 * KSTR];
    __shared__ __align__(16) bf16 Vl[64 * KSTR];

    const int tid  = threadIdx.x;
    const int wid  = tid >> 5;
    const int lane = tid & 31;
    const int lr = lane >> 2;
    const int lc = lane & 3;

    const int qt = blockIdx.x;
    const int h  = blockIdx.y;
    const int b  = blockIdx.z;
    const int kv = h >> 2;
    const int q0 = qt * 128;
    const int wrow = q0 + wid * 16;     // warp's first q row

    // Q fragments (persist across the whole KV loop)
    uint32_t qfh[4][4], qfl[4][4];
    {
        const bf16* Qh = qhi + (((size_t)b * NH_ + h) * S_ + wrow) * HD_;
        const bf16* Ql = qlo + (((size_t)b * NH_ + h) * S_ + wrow) * HD_;
        #pragma unroll
        for (int kc = 0; kc < 4; kc++) {
            int c = kc * 16 + lc * 2;
            qfh[kc][0] = *(const uint32_t*)(Qh + lr * HD_ + c);
            qfh[kc][1] = *(const uint32_t*)(Qh + (lr + 8) * HD_ + c);
            qfh[kc][2] = *(const uint32_t*)(Qh + lr * HD_ + c + 8);
            qfh[kc][3] = *(const uint32_t*)(Qh + (lr + 8) * HD_ + c + 8);
            qfl[kc][0] = *(const uint32_t*)(Ql + lr * HD_ + c);
            qfl[kc][1] = *(const uint32_t*)(Ql + (lr + 8) * HD_ + c);
            qfl[kc][2] = *(const uint32_t*)(Ql + lr * HD_ + c + 8);
            qfl[kc][3] = *(const uint32_t*)(Ql + (lr + 8) * HD_ + c + 8);
        }
    }

    float m0 = -1e30f, m1 = -1e30f, l0 = 0.f, l1 = 0.f;
    float Oa[8][4];
    #pragma unroll
    for (int i = 0; i < 8; i++)
        #pragma unroll
        for (int j = 0; j < 4; j++) Oa[i][j] = 0.f;

    const bf16* Kbh = khi  + ((size_t)b * NKV_ + kv) * S_ * HD_;
    const bf16* Kbl = klo  + ((size_t)b * NKV_ + kv) * S_ * HD_;
    const bf16* Vbh = vthi + ((size_t)b * NKV_ + kv) * (size_t)HD_ * S_;
    const bf16* Vbl = vtlo + ((size_t)b * NKV_ + kv) * (size_t)HD_ * S_;

    const int jend = 2 * qt + 1;
    const int lrow = tid >> 3;            // 0..31
    const int lcol = (tid & 7) * 8;

    for (int j = 0; j <= jend; j++) {
        __syncthreads();
        #pragma unroll
        for (int q = 0; q < 2; q++) {
            int r = lrow + q * 32;
            *(uint4*)(Kh + r * KSTR + lcol) = *(const uint4*)(Kbh + (size_t)(j * 64 + r) * HD_ + lcol);
            *(uint4*)(Kl + r * KSTR + lcol) = *(const uint4*)(Kbl + (size_t)(j * 64 + r) * HD_ + lcol);
            *(uint4*)(Vh + r * KSTR + lcol) = *(const uint4*)(Vbh + (size_t)r * S_ + j * 64 + lcol);
            *(uint4*)(Vl + r * KSTR + lcol) = *(const uint4*)(Vbl + (size_t)r * S_ + j * 64 + lcol);
        }
        __syncthreads();

        if (j * 64 > wrow + 15) continue;   // fully masked for this warp

        // ---- S = Q K^T (split 3-product) ----
        float Sa[8][4];
        #pragma unroll
        for (int i = 0; i < 8; i++)
            #pragma unroll
            for (int c = 0; c < 4; c++) Sa[i][c] = 0.f;

        #pragma unroll
        for (int kc = 0; kc < 4; kc++) {
            #pragma unroll
            for (int nt = 0; nt < 8; nt++) {
                const bf16* bh = Kh + (nt * 8 + lr) * KSTR + kc * 16 + lc * 2;
                const bf16* bl = Kl + (nt * 8 + lr) * KSTR + kc * 16 + lc * 2;
                uint32_t bh0 = *(const uint32_t*)(bh);
                uint32_t bh1 = *(const uint32_t*)(bh + 8);
                uint32_t bl0 = *(const uint32_t*)(bl);
                uint32_t bl1 = *(const uint32_t*)(bl + 8);
                asm volatile(
                    "mma.sync.aligned.m16n8k16.row.col.f32.bf16.bf16.f32 "
                    "{%0,%1,%2,%3}, {%4,%5,%6,%7}, {%8,%9}, {%0,%1,%2,%3};"
                    : "+f"(Sa[nt][0]), "+f"(Sa[nt][1]), "+f"(Sa[nt][2]), "+f"(Sa[nt][3])
                    : "r"(qfh[kc][0]), "r"(qfh[kc][1]), "r"(qfh[kc][2]), "r"(qfh[kc][3]),
                      "r"(bh0), "r"(bh1));
                asm volatile(
                    "mma.sync.aligned.m16n8k16.row.col.f32.bf16.bf16.f32 "
                    "{%0,%1,%2,%3}, {%4,%5,%6,%7}, {%8,%9}, {%0,%1,%2,%3};"
                    : "+f"(Sa[nt][0]), "+f"(Sa[nt][1]), "+f"(Sa[nt][2]), "+f"(Sa[nt][3])
                    : "r"(qfh[kc][0]), "r"(qfh[kc][1]), "r"(qfh[kc][2]), "r"(qfh[kc][3]),
                      "r"(bl0), "r"(bl1));
                asm volatile(
                    "mma.sync.aligned.m16n8k16.row.col.f32.bf16.bf16.f32 "
                    "{%0,%1,%2,%3}, {%4,%5,%6,%7}, {%8,%9}, {%0,%1,%2,%3};"
                    : "+f"(Sa[nt][0]), "+f"(Sa[nt][1]), "+f"(Sa[nt][2]), "+f"(Sa[nt][3])
                    : "r"(qfl[kc][0]), "r"(qfl[kc][1]), "r"(qfl[kc][2]), "r"(qfl[kc][3]),
                      "r"(bh0), "r"(bh1));
            }
        }

        // ---- causal mask ----
        if (j * 64 + 63 > wrow) {
            int s0 = wrow + lr, s1 = s0 + 8;
            #pragma unroll
            for (int nt = 0; nt < 8; nt++) {
                int t0 = j * 64 + nt * 8 + lc * 2;
                if (t0     > s0) Sa[nt][0] = -1e30f;
                if (t0 + 1 > s0) Sa[nt][1] = -1e30f;
                if (t0     > s1) Sa[nt][2] = -1e30f;
                if (t0 + 1 > s1) Sa[nt][3] = -1e30f;
            }
        }

        // ---- online softmax (quad-local) ----
        float mt0 = -1e30f, mt1 = -1e30f;
        #pragma unroll
        for (int nt = 0; nt < 8; nt++) {
            mt0 = fmaxf(mt0, fmaxf(Sa[nt][0], Sa[nt][1]));
            mt1 = fmaxf(mt1, fmaxf(Sa[nt][2], Sa[nt][3]));
        }
        mt0 = fmaxf(mt0, __shfl_xor_sync(0xffffffffu, mt0, 1));
        mt0 = fmaxf(mt0, __shfl_xor_sync(0xffffffffu, mt0, 2));
        mt1 = fmaxf(mt1, __shfl_xor_sync(0xffffffffu, mt1, 1));
        mt1 = fmaxf(mt1, __shfl_xor_sync(0xffffffffu, mt1, 2));
        float mn0 = fmaxf(m0, mt0), mn1 = fmaxf(m1, mt1);
        float a0 = __expf(m0 - mn0), a1 = __expf(m1 - mn1);
        m0 = mn0; m1 = mn1;

        float ps0 = 0.f, ps1 = 0.f;
        uint32_t pfh[4][4], pfl[4][4];
        #pragma unroll
        for (int nt = 0; nt < 8; nt++) {
            float p0 = __expf(Sa[nt][0] - m0);
            float p1 = __expf(Sa[nt][1] - m0);
            float p2 = __expf(Sa[nt][2] - m1);
            float p3 = __expf(Sa[nt][3] - m1);
            ps0 += p0 + p1;
            ps1 += p2 + p3;
            bf16 h0 = __float2bfloat16(p0), h1b = __float2bfloat16(p1);
            bf16 h2 = __float2bfloat16(p2), h3 = __float2bfloat16(p3);
            bf16 e0 = __float2bfloat16(p0 - __bfloat162float(h0));
            bf16 e1 = __float2bfloat16(p1 - __bfloat162float(h1b));
            bf16 e2 = __float2bfloat16(p2 - __bfloat162float(h2));
            bf16 e3 = __float2bfloat16(p3 - __bfloat162float(h3));
            __nv_bfloat162 ph01 = __nv_bfloat162(h0, h1b);
            __nv_bfloat162 ph23 = __nv_bfloat162(h2, h3);
            __nv_bfloat162 pl01 = __nv_bfloat162(e0, e1);
            __nv_bfloat162 pl23 = __nv_bfloat162(e2, e3);
            int kc = nt >> 1;
            if ((nt & 1) == 0) {
                pfh[kc][0] = *(uint32_t*)&ph01;
                pfh[kc][1] = *(uint32_t*)&ph23;
                pfl[kc][0] = *(uint32_t*)&pl01;
                pfl[kc][1] = *(uint32_t*)&pl23;
            } else {
                pfh[kc][2] = *(uint32_t*)&ph01;
                pfh[kc][3] = *(uint32_t*)&ph23;
                pfl[kc][2] = *(uint32_t*)&pl01;
                pfl[kc][3] = *(uint32_t*)&pl23;
            }
        }
        ps0 += __shfl_xor_sync(0xffffffffu, ps0, 1);
        ps0 += __shfl_xor_sync(0xffffffffu, ps0, 2);
        ps1 += __shfl_xor_sync(0xffffffffu, ps1, 1);
        ps1 += __shfl_xor_sync(0xffffffffu, ps1, 2);
        l0 = l0 * a0 + ps0;
        l1 = l1 * a1 + ps1;

        #pragma unroll
        for (int dt = 0; dt < 8; dt++) {
            Oa[dt][0] *= a0; Oa[dt][1] *= a0;
            Oa[dt][2] *= a1; Oa[dt][3] *= a1;
        }

        // ---- O += P V (split 3-product) ----
        #pragma unroll
        for (int kc = 0; kc < 4; kc++) {
            #pragma unroll
            for (int dt = 0; dt < 8; dt++) {
                const bf16* vh = Vh + (dt * 8 + lr) * KSTR + kc * 16 + lc * 2;
                const bf16* vl = Vl + (dt * 8 + lr) * KSTR + kc * 16 + lc * 2;
                uint32_t vh0 = *(const uint32_t*)(vh);
                uint32_t vh1 = *(const uint32_t*)(vh + 8);
                uint32_t vl0 = *(const uint32_t*)(vl);
                uint32_t vl1 = *(const uint32_t*)(vl + 8);
                asm volatile(
                    "mma.sync.aligned.m16n8k16.row.col.f32.bf16.bf16.f32 "
                    "{%0,%1,%2,%3}, {%4,%5,%6,%7}, {%8,%9}, {%0,%1,%2,%3};"
                    : "+f"(Oa[dt][0]), "+f"(Oa[dt][1]), "+f"(Oa[dt][2]), "+f"(Oa[dt][3])
                    : "r"(pfh[kc][0]), "r"(pfh[kc][1]), "r"(pfh[kc][2]), "r"(pfh[kc][3]),
                      "r"(vh0), "r"(vh1));
                asm volatile(
                    "mma.sync.aligned.m16n8k16.row.col.f32.bf16.bf16.f32 "
                    "{%0,%1,%2,%3}, {%4,%5,%6,%7}, {%8,%9}, {%0,%1,%2,%3};"
                    : "+f"(Oa[dt][0]), "+f"(Oa[dt][1]), "+f"(Oa[dt][2]), "+f"(Oa[dt][3])
                    : "r"(pfh[kc][0]), "r"(pfh[kc][1]), "r"(pfh[kc][2]), "r"(pfh[kc][3]),
                      "r"(vl0), "r"(vl1));
                asm volatile(
                    "mma.sync.aligned.m16n8k16.row.col.f32.bf16.bf16.f32 "
                    "{%0,%1,%2,%3}, {%4,%5,%6,%7}, {%8,%9}, {%0,%1,%2,%3};"
                    : "+f"(Oa[dt][0]), "+f"(Oa[dt][1]), "+f"(Oa[dt][2]), "+f"(Oa[dt][3])
                    : "r"(pfl[kc][0]), "r"(pfl[kc][1]), "r"(pfl[kc][2]), "r"(pfl[kc][3]),
                      "r"(vh0), "r"(vh1));
            }
        }
    }

    // ---- epilogue: normalize + split-write bf16 hi/lo for Wo GEMM ----
    float inv0 = 1.f / l0, inv1 = 1.f / l1;
    int s0 = wrow + lr;
    #pragma unroll
    for (int dt = 0; dt < 8; dt++) {
        int col = h * HD_ + dt * 8 + lc * 2;
        float o00 = Oa[dt][0] * inv0, o01 = Oa[dt][1] * inv0;
        float o10 = Oa[dt][2] * inv1, o11 = Oa[dt][3] * inv1;
        bf16 h00 = __float2bfloat16(o00), h01 = __float2bfloat16(o01);
        bf16 h10 = __float2bfloat16(o10), h11 = __float2bfloat16(o11);
        __nv_bfloat162 hi0 = __nv_bfloat162(h00, h01);
        __nv_bfloat162 hi1 = __nv_bfloat162(h10, h11);
        __nv_bfloat162 lo0 = __nv_bfloat162(__float2bfloat16(o00 - __bfloat162float(h00)),
                                            __float2bfloat16(o01 - __bfloat162float(h01)));
        __nv_bfloat162 lo1 = __nv_bfloat162(__float2bfloat16(o10 - __bfloat162float(h10)),
                                            __float2bfloat16(o11 - __bfloat162float(h11)));
        *(uint32_t*)(ohi + ((size_t)(b * S_ + s0)) * E_ + col)     = *(uint32_t*)&hi0;
        *(uint32_t*)(ohi + ((size_t)(b * S_ + s0 + 8)) * E_ + col) = *(uint32_t*)&hi1;
        *(uint32_t*)(olo + ((size_t)(b * S_ + s0)) * E_ + col)     = *(uint32_t*)&lo0;
        *(uint32_t*)(olo + ((size_t)(b * S_ + s0 + 8)) * E_ + col) = *(uint32_t*)&lo1;
    }
}

// ---------------- launch ---------------------------------------------------
extern "C" void kernel_launch(void* const* d_in, const int* in_sizes, int n_in,
                              void* d_out, int out_size)
{
    const float* x    = (const float*)d_in[0];
    const float* cosT = (const float*)d_in[2];
    const float* sinT = (const float*)d_in[3];
    const float* Wq   = (const float*)d_in[4];
    const float* Wk   = (const float*)d_in[5];
    const float* Wv   = (const float*)d_in[6];
    const float* Wo   = (const float*)d_in[7];

    float* out  = (float*)d_out;
    float* outK = out + (size_t)B_ * S_ * E_;
    float* outV = outK + (size_t)B_ * NKV_ * S_ * HD_;

    float *gq, *gk, *gv;
    bf16 *ahi, *alo, *wqhi, *wqlo, *wkhi, *wklo, *wvhi, *wvlo, *wohi, *wolo;
    bf16 *qhi, *qlo, *khi, *klo, *vthi, *vtlo;
    cudaGetSymbolAddress((void**)&gq,    g_q);
    cudaGetSymbolAddress((void**)&gk,    g_k);
    cudaGetSymbolAddress((void**)&gv,    g_v);
    cudaGetSymbolAddress((void**)&ahi,   g_ahi);
    cudaGetSymbolAddress((void**)&alo,   g_alo);
    cudaGetSymbolAddress((void**)&wqhi,  g_wqhi);
    cudaGetSymbolAddress((void**)&wqlo,  g_wqlo);
    cudaGetSymbolAddress((void**)&wkhi,  g_wkhi);
    cudaGetSymbolAddress((void**)&wklo,  g_wklo);
    cudaGetSymbolAddress((void**)&wvhi,  g_wvhi);
    cudaGetSymbolAddress((void**)&wvlo,  g_wvlo);
    cudaGetSymbolAddress((void**)&wohi,  g_wohi);
    cudaGetSymbolAddress((void**)&wolo,  g_wolo);
    cudaGetSymbolAddress((void**)&qhi,   g_qhi);
    cudaGetSymbolAddress((void**)&qlo,   g_qlo);
    cudaGetSymbolAddress((void**)&khi,   g_khi);
    cudaGetSymbolAddress((void**)&klo,   g_klo);
    cudaGetSymbolAddress((void**)&vthi,  g_vthi);
    cudaGetSymbolAddress((void**)&vtlo,  g_vtlo);

    // weight conversions
    {
        dim3 thr(32, 8);
        splitT_kernel<<<dim3(E_ / 32, E_ / 32), thr>>>(Wq, wqhi, wqlo, E_, E_);
        splitT_kernel<<<dim3((NKV_*HD_) / 32, E_ / 32), thr>>>(Wk, wkhi, wklo, E_, NKV_*HD_);
        splitT_kernel<<<dim3((NKV_*HD_) / 32, E_ / 32), thr>>>(Wv, wvhi, wvlo, E_, NKV_*HD_);
        splitT_kernel<<<dim3(E_ / 32, E_ / 32), thr>>>(Wo, wohi, wolo, E_, E_);
    }
    // activation conversion
    {
        int n = MROWS * E_;
        split_kernel<<<(n + 255) / 256, 256>>>(x, ahi, alo, n);
    }

    // projections
    gemm_bf16_split<<<dim3(E_ / BN, MROWS / BM), 256>>>(ahi, alo, wqhi, wqlo, gq, MROWS, E_, E_);
    gemm_bf16_split<<<dim3((NKV_*HD_) / BN, MROWS / BM), 256>>>(ahi, alo, wkhi, wklo, gk, MROWS, NKV_*HD_, E_);
    gemm_bf16_split<<<dim3((NKV_*HD_) / BN, MROWS / BM), 256>>>(ahi, alo, wvhi, wvlo, gv, MROWS, NKV_*HD_, E_);

    // rope + transposes + splits
    {
        int tq = B_ * S_ * NH_ * 32;
        rope_q_kernel<<<(tq + 255) / 256, 256>>>(gq, cosT, sinT, qhi, qlo);
        int tk = B_ * S_ * NKV_ * 32;
        rope_k_kernel<<<(tk + 255) / 256, 256>>>(gk, cosT, sinT, outK, khi, klo);
        int tv = B_ * S_ * 128;
        copy_v_kernel<<<(tv + 255) / 256, 256>>>(gv, outV);
        vT_split_kernel<<<dim3(S_ / 32, B_ * NKV_), 256>>>(gv, vthi, vtlo);
    }

    // flash attention (tensor core) -> writes ahi/alo directly
    {
        dim3 grid(S_ / 128, NH_, B_);
        flash_mma<<<grid, 256>>>(qhi, qlo, khi, klo, vthi, vtlo, ahi, alo);
    }

    // output projection
    gemm_bf16_split<<<dim3(E_ / BN, MROWS / BM), 256>>>(ahi, alo, wohi, wolo, out, MROWS, E_, E_);
}

// round 5
// speedup vs baseline: 3.3807x; 1.2356x over previous
#include <cuda_runtime.h>
#include <cuda_bf16.h>
#include <cstdint>

// Problem constants
#define B_   2
#define S_   2048
#define E_   2048
#define NH_  32
#define NKV_ 8
#define HD_  64
#define GRP_ 4
#define MROWS (B_*S_)     // 4096
#define NQKV 3072         // 2048 + 512 + 512

typedef __nv_bfloat16 bf16;

// ---------------- scratch (device globals; no allocation) ----------------
__device__ float g_qkv [MROWS*NQKV];        // fused q|k|v projection

__device__ __align__(16) bf16 g_ahi[MROWS*E_];
__device__ __align__(16) bf16 g_alo[MROWS*E_];
__device__ __align__(16) bf16 g_wqkvhi[NQKV*E_];   // [N,K] transposed
__device__ __align__(16) bf16 g_wqkvlo[NQKV*E_];
__device__ __align__(16) bf16 g_wohi[E_*E_];
__device__ __align__(16) bf16 g_wolo[E_*E_];

__device__ __align__(16) bf16 g_qhi[B_*NH_*S_*HD_];
__device__ __align__(16) bf16 g_qlo[B_*NH_*S_*HD_];
__device__ __align__(16) bf16 g_khi[B_*NKV_*S_*HD_];
__device__ __align__(16) bf16 g_klo[B_*NKV_*S_*HD_];
__device__ __align__(16) bf16 g_vthi[B_*NKV_*HD_*S_];
__device__ __align__(16) bf16 g_vtlo[B_*NKV_*HD_*S_];

// ---------------- helpers --------------------------------------------------
__device__ __forceinline__ uint32_t smem_u32(const void* p) {
    uint32_t a;
    asm("{ .reg .u64 t; cvta.to.shared.u64 t, %1; cvt.u32.u64 %0, t; }"
        : "=r"(a) : "l"(p));
    return a;
}

__device__ __forceinline__ void cp_async16(void* smem, const void* gmem) {
    uint32_t s = smem_u32(smem);
    asm volatile("cp.async.cg.shared.global [%0], [%1], 16;" :: "r"(s), "l"(gmem));
}
__device__ __forceinline__ void cp_commit() {
    asm volatile("cp.async.commit_group;" ::: "memory");
}
__device__ __forceinline__ void cp_wait1() {
    asm volatile("cp.async.wait_group 1;" ::: "memory");
}

__device__ __forceinline__ void ldm_x4(uint32_t* r, uint32_t addr) {
    asm volatile("ldmatrix.sync.aligned.m8n8.x4.shared.b16 {%0,%1,%2,%3}, [%4];"
                 : "=r"(r[0]), "=r"(r[1]), "=r"(r[2]), "=r"(r[3]) : "r"(addr));
}

// ---------------- split conversion kernels -------------------------------
__global__ void split_kernel(const float* __restrict__ in,
                             bf16* __restrict__ hi, bf16* __restrict__ lo, int n)
{
    int i = blockIdx.x * blockDim.x + threadIdx.x;
    if (i >= n) return;
    float x = in[i];
    bf16 h = __float2bfloat16(x);
    hi[i] = h;
    lo[i] = __float2bfloat16(x - __bfloat162float(h));
}

// fp32 W [K,N] -> transposed hi/lo bf16 [N,K] (written at row offset)
__global__ void splitT_kernel(const float* __restrict__ in,
                              bf16* __restrict__ hiT, bf16* __restrict__ loT,
                              int K, int N)
{
    __shared__ float t[32][33];
    int kb = blockIdx.y * 32, nb = blockIdx.x * 32;
    #pragma unroll
    for (int r = threadIdx.y; r < 32; r += 8)
        t[r][threadIdx.x] = in[(size_t)(kb + r) * N + nb + threadIdx.x];
    __syncthreads();
    #pragma unroll
    for (int r = threadIdx.y; r < 32; r += 8) {
        float x = t[threadIdx.x][r];
        bf16 h = __float2bfloat16(x);
        size_t o = (size_t)(nb + r) * K + kb + threadIdx.x;
        hiT[o] = h;
        loT[o] = __float2bfloat16(x - __bfloat162float(h));
    }
}

// ---------------- split-bf16 tensor-core GEMM, cp.async pipelined ----------
// C[M,N] fp32 = Ahi*Bhi^T + Ahi*Blo^T + Alo*Bhi^T ; A [M,K], B^T [N,K]
#define BKT 32
#define AST 40                        // bf16 stride (40*2=80B rows)
#define STAGE_A_BYTES (128 * AST * 2) // 10240
#define STAGE_BYTES   (2 * STAGE_A_BYTES)
#define STAGES 3
#define GEMM_SMEM (STAGES * STAGE_BYTES)

__global__ __launch_bounds__(256)
void gemm_pipe(const bf16* __restrict__ Ahi, const bf16* __restrict__ Alo,
               const bf16* __restrict__ BhiT, const bf16* __restrict__ BloT,
               float* __restrict__ C, int M, int N, int K)
{
    extern __shared__ __align__(16) char gsm[];

    const int tid  = threadIdx.x;
    const int wid  = tid >> 5;
    const int lane = tid & 31;
    const int wm = (wid >> 2) * 64;
    const int wn = (wid & 3) * 32;
    const int m0 = blockIdx.y * 128;
    const int n0 = blockIdx.x * 128;

    const int lr = lane >> 2;
    const int lc = (lane & 3) * 2;

    const bf16* segA[3] = {Ahi, Ahi, Alo};
    const bf16* segB[3] = {BhiT, BloT, BhiT};
    const int KIT = K / BKT;
    const int NIT = 3 * KIT;

    // copy mapping: 512 16B-chunks per tile; thread does 2 A + 2 B
    const int crow0 = tid >> 1, cu0 = (tid & 1) * 2;        // rows 0..127, u 0/2
    // (each thread copies u and u+1 chunk: 2x16B at (crow0, cu0) and (crow0, cu0+1))

    auto issue = [&](int it) {
        int seg = it / KIT;
        int k0  = (it - seg * KIT) * BKT;
        const bf16* Ap = segA[seg] + (size_t)(m0 + crow0) * K + k0;
        const bf16* Bp = segB[seg] + (size_t)(n0 + crow0) * K + k0;
        char* sA = gsm + (it % STAGES) * STAGE_BYTES;
        char* sB = sA + STAGE_A_BYTES;
        char* dA = sA + crow0 * (AST * 2) + cu0 * 16;
        char* dB = sB + crow0 * (AST * 2) + cu0 * 16;
        cp_async16(dA,      Ap + cu0 * 8);
        cp_async16(dA + 16, Ap + cu0 * 8 + 8);
        cp_async16(dB,      Bp + cu0 * 8);
        cp_async16(dB + 16, Bp + cu0 * 8 + 8);
        cp_commit();
    };

    float acc[4][4][4];
    #pragma unroll
    for (int i = 0; i < 4; i++)
        #pragma unroll
        for (int j = 0; j < 4; j++)
            #pragma unroll
            for (int r = 0; r < 4; r++) acc[i][j][r] = 0.f;

    issue(0);
    issue(1);

    // ldmatrix lane addressing (byte offsets within stage)
    const int a_row = (lane & 7) + ((lane >> 3) & 1) * 8;   // 0..15
    const int a_kad = (lane >> 4) * 8;                      // 0/8
    const int b_row = (lane & 7) + (lane >> 4) * 8;         // 0..15
    const int b_kad = ((lane >> 3) & 1) * 8;                // 0/8

    for (int it = 0; it < NIT; ++it) {
        cp_wait1();
        __syncthreads();
        if (it + 2 < NIT) issue(it + 2);

        uint32_t sAu = smem_u32(gsm + (it % STAGES) * STAGE_BYTES);
        uint32_t sBu = sAu + STAGE_A_BYTES;

        #pragma unroll
        for (int ks = 0; ks < 2; ks++) {
            const int kb = ks * 16;
            uint32_t af[4][4];
            #pragma unroll
            for (int mt = 0; mt < 4; mt++) {
                uint32_t addr = sAu + ((wm + mt * 16 + a_row) * AST + kb + a_kad) * 2;
                ldm_x4(af[mt], addr);
            }
            uint32_t bfg[4][4];   // [pair][4 regs] -> nt = 2p (+0,1), 2p+1 (+2,3)
            #pragma unroll
            for (int p = 0; p < 2; p++) {
                uint32_t addr = sBu + ((wn + p * 16 + b_row) * AST + kb + b_kad) * 2;
                ldm_x4(bfg[p], addr);
            }
            #pragma unroll
            for (int mt = 0; mt < 4; mt++)
                #pragma unroll
                for (int nt = 0; nt < 4; nt++) {
                    const uint32_t b0 = bfg[nt >> 1][(nt & 1) * 2];
                    const uint32_t b1 = bfg[nt >> 1][(nt & 1) * 2 + 1];
                    asm volatile(
                        "mma.sync.aligned.m16n8k16.row.col.f32.bf16.bf16.f32 "
                        "{%0,%1,%2,%3}, {%4,%5,%6,%7}, {%8,%9}, {%0,%1,%2,%3};"
                        : "+f"(acc[mt][nt][0]), "+f"(acc[mt][nt][1]),
                          "+f"(acc[mt][nt][2]), "+f"(acc[mt][nt][3])
                        : "r"(af[mt][0]), "r"(af[mt][1]), "r"(af[mt][2]), "r"(af[mt][3]),
                          "r"(b0), "r"(b1));
                }
        }
    }

    #pragma unroll
    for (int mt = 0; mt < 4; mt++) {
        #pragma unroll
        for (int nt = 0; nt < 4; nt++) {
            int r = m0 + wm + mt * 16 + lr;
            int c = n0 + wn + nt * 8 + lc;
            *(float2*)(C + (size_t)r * N + c) =
                make_float2(acc[mt][nt][0], acc[mt][nt][1]);
            *(float2*)(C + (size_t)(r + 8) * N + c) =
                make_float2(acc[mt][nt][2], acc[mt][nt][3]);
        }
    }
}

// ---------------- RoPE + transpose kernels (read fused QKV, stride 3072) ---
__global__ void rope_q_kernel(const float* __restrict__ qkv,
                              const float* __restrict__ cosT,
                              const float* __restrict__ sinT,
                              bf16* __restrict__ qhi, bf16* __restrict__ qlo)
{
    int idx = blockIdx.x * blockDim.x + threadIdx.x;
    if (idx >= B_ * S_ * NH_ * 32) return;
    int d = idx & 31;
    int h = (idx >> 5) & (NH_ - 1);
    int s = (idx >> 10) & (S_ - 1);
    int b = idx >> 21;
    const float* src = qkv + ((size_t)(b * S_ + s)) * NQKV + h * HD_;
    float x1 = src[d], x2 = src[d + 32];
    float c  = cosT[s * HD_ + d];
    float sn = sinT[s * HD_ + d];
    float y1 = (x1 * c - x2 * sn) * 0.125f;
    float y2 = (x2 * c + x1 * sn) * 0.125f;
    size_t o = (((size_t)b * NH_ + h) * S_ + s) * HD_;
    bf16 h1 = __float2bfloat16(y1);
    bf16 h2 = __float2bfloat16(y2);
    qhi[o + d]      = h1;
    qhi[o + d + 32] = h2;
    qlo[o + d]      = __float2bfloat16(y1 - __bfloat162float(h1));
    qlo[o + d + 32] = __float2bfloat16(y2 - __bfloat162float(h2));
}

__global__ void rope_k_kernel(const float* __restrict__ qkv,
                              const float* __restrict__ cosT,
                              const float* __restrict__ sinT,
                              float* __restrict__ kt,
                              bf16* __restrict__ khi, bf16* __restrict__ klo)
{
    int idx = blockIdx.x * blockDim.x + threadIdx.x;
    if (idx >= B_ * S_ * NKV_ * 32) return;
    int d = idx & 31;
    int h = (idx >> 5) & (NKV_ - 1);
    int s = (idx >> 8) & (S_ - 1);
    int b = idx >> 19;
    const float* src = qkv + ((size_t)(b * S_ + s)) * NQKV + E_ + h * HD_;
    float x1 = src[d], x2 = src[d + 32];
    float c  = cosT[s * HD_ + d];
    float sn = sinT[s * HD_ + d];
    float y1 = x1 * c - x2 * sn;
    float y2 = x2 * c + x1 * sn;
    size_t o = (((size_t)b * NKV_ + h) * S_ + s) * HD_;
    kt[o + d]      = y1;
    kt[o + d + 32] = y2;
    bf16 h1 = __float2bfloat16(y1);
    bf16 h2 = __float2bfloat16(y2);
    khi[o + d]      = h1;
    khi[o + d + 32] = h2;
    klo[o + d]      = __float2bfloat16(y1 - __bfloat162float(h1));
    klo[o + d + 32] = __float2bfloat16(y2 - __bfloat162float(h2));
}

__global__ void copy_v_kernel(const float* __restrict__ qkv, float* __restrict__ vt)
{
    int idx = blockIdx.x * blockDim.x + threadIdx.x;
    if (idx >= B_ * S_ * 128) return;
    int e4 = idx & 127;
    int s  = (idx >> 7) & (S_ - 1);
    int b  = idx >> 18;
    int e  = e4 * 4;
    int h  = e >> 6;
    int d  = e & 63;
    float4 v = *(const float4*)(qkv + ((size_t)(b * S_ + s)) * NQKV + E_ + NKV_ * HD_ + e);
    *(float4*)(vt + (((size_t)b * NKV_ + h) * S_ + s) * HD_ + d) = v;
}

__global__ void vT_split_kernel(const float* __restrict__ qkv,
                                bf16* __restrict__ vthi, bf16* __restrict__ vtlo)
{
    __shared__ float t[64][33];
    int s0 = blockIdx.x * 32;
    int kvb = blockIdx.y;
    int b  = kvb / NKV_;
    int kv = kvb % NKV_;
    int tid = threadIdx.x;
    for (int l = tid; l < 32 * 16; l += 256) {
        int s = l >> 4, d4 = (l & 15) * 4;
        float4 v = *(const float4*)(qkv + ((size_t)(b * S_ + s0 + s)) * NQKV
                                    + E_ + NKV_ * HD_ + kv * HD_ + d4);
        t[d4 + 0][s] = v.x;
        t[d4 + 1][s] = v.y;
        t[d4 + 2][s] = v.z;
        t[d4 + 3][s] = v.w;
    }
    __syncthreads();
    for (int l = tid; l < 64 * 32; l += 256) {
        int d = l >> 5, s = l & 31;
        float x = t[d][s];
        bf16 h = __float2bfloat16(x);
        size_t o = (((size_t)b * NKV_ + kv) * HD_ + d) * S_ + s0 + s;
        vthi[o] = h;
        vtlo[o] = __float2bfloat16(x - __bfloat162float(h));
    }
}

// ---------------- Flash attention (mma.sync, split-bf16) -------------------
#define KSTR 72
__global__ __launch_bounds__(256)
void flash_mma(const bf16* __restrict__ qhi, const bf16* __restrict__ qlo,
               const bf16* __restrict__ khi, const bf16* __restrict__ klo,
               const bf16* __restrict__ vthi, const bf16* __restrict__ vtlo,
               bf16* __restrict__ ohi, bf16* __restrict__ olo)
{
    __shared__ __align__(16) bf16 Kh[64 * KSTR];
    __shared__ __align__(16) bf16 Kl[64 * KSTR];
    __shared__ __align__(16) bf16 Vh[64 * KSTR];
    __shared__ __align__(16) bf16 Vl[64 * KSTR];

    const int tid  = threadIdx.x;
    const int wid  = tid >> 5;
    const int lane = tid & 31;
    const int lr = lane >> 2;
    const int lc = lane & 3;

    const int qt = blockIdx.x;
    const int h  = blockIdx.y;
    const int b  = blockIdx.z;
    const int kv = h >> 2;
    const int q0 = qt * 128;
    const int wrow = q0 + wid * 16;

    uint32_t qfh[4][4], qfl[4][4];
    {
        const bf16* Qh = qhi + (((size_t)b * NH_ + h) * S_ + wrow) * HD_;
        const bf16* Ql = qlo + (((size_t)b * NH_ + h) * S_ + wrow) * HD_;
        #pragma unroll
        for (int kc = 0; kc < 4; kc++) {
            int c = kc * 16 + lc * 2;
            qfh[kc][0] = *(const uint32_t*)(Qh + lr * HD_ + c);
            qfh[kc][1] = *(const uint32_t*)(Qh + (lr + 8) * HD_ + c);
            qfh[kc][2] = *(const uint32_t*)(Qh + lr * HD_ + c + 8);
            qfh[kc][3] = *(const uint32_t*)(Qh + (lr + 8) * HD_ + c + 8);
            qfl[kc][0] = *(const uint32_t*)(Ql + lr * HD_ + c);
            qfl[kc][1] = *(const uint32_t*)(Ql + (lr + 8) * HD_ + c);
            qfl[kc][2] = *(const uint32_t*)(Ql + lr * HD_ + c + 8);
            qfl[kc][3] = *(const uint32_t*)(Ql + (lr + 8) * HD_ + c + 8);
        }
    }

    float m0 = -1e30f, m1 = -1e30f, l0 = 0.f, l1 = 0.f;
    float Oa[8][4];
    #pragma unroll
    for (int i = 0; i < 8; i++)
        #pragma unroll
        for (int j = 0; j < 4; j++) Oa[i][j] = 0.f;

    const bf16* Kbh = khi  + ((size_t)b * NKV_ + kv) * S_ * HD_;
    const bf16* Kbl = klo  + ((size_t)b * NKV_ + kv) * S_ * HD_;
    const bf16* Vbh = vthi + ((size_t)b * NKV_ + kv) * (size_t)HD_ * S_;
    const bf16* Vbl = vtlo + ((size_t)b * NKV_ + kv) * (size_t)HD_ * S_;

    const int jend = 2 * qt + 1;
    const int lrow = tid >> 3;
    const int lcol = (tid & 7) * 8;

    for (int j = 0; j <= jend; j++) {
        __syncthreads();
        #pragma unroll
        for (int q = 0; q < 2; q++) {
            int r = lrow + q * 32;
            *(uint4*)(Kh + r * KSTR + lcol) = *(const uint4*)(Kbh + (size_t)(j * 64 + r) * HD_ + lcol);
            *(uint4*)(Kl + r * KSTR + lcol) = *(const uint4*)(Kbl + (size_t)(j * 64 + r) * HD_ + lcol);
            *(uint4*)(Vh + r * KSTR + lcol) = *(const uint4*)(Vbh + (size_t)r * S_ + j * 64 + lcol);
            *(uint4*)(Vl + r * KSTR + lcol) = *(const uint4*)(Vbl + (size_t)r * S_ + j * 64 + lcol);
        }
        __syncthreads();

        if (j * 64 > wrow + 15) continue;

        float Sa[8][4];
        #pragma unroll
        for (int i = 0; i < 8; i++)
            #pragma unroll
            for (int c = 0; c < 4; c++) Sa[i][c] = 0.f;

        #pragma unroll
        for (int kc = 0; kc < 4; kc++) {
            #pragma unroll
            for (int nt = 0; nt < 8; nt++) {
                const bf16* bh = Kh + (nt * 8 + lr) * KSTR + kc * 16 + lc * 2;
                const bf16* bl = Kl + (nt * 8 + lr) * KSTR + kc * 16 + lc * 2;
                uint32_t bh0 = *(const uint32_t*)(bh);
                uint32_t bh1 = *(const uint32_t*)(bh + 8);
                uint32_t bl0 = *(const uint32_t*)(bl);
                uint32_t bl1 = *(const uint32_t*)(bl + 8);
                asm volatile(
                    "mma.sync.aligned.m16n8k16.row.col.f32.bf16.bf16.f32 "
                    "{%0,%1,%2,%3}, {%4,%5,%6,%7}, {%8,%9}, {%0,%1,%2,%3};"
                    : "+f"(Sa[nt][0]), "+f"(Sa[nt][1]), "+f"(Sa[nt][2]), "+f"(Sa[nt][3])
                    : "r"(qfh[kc][0]), "r"(qfh[kc][1]), "r"(qfh[kc][2]), "r"(qfh[kc][3]),
                      "r"(bh0), "r"(bh1));
                asm volatile(
                    "mma.sync.aligned.m16n8k16.row.col.f32.bf16.bf16.f32 "
                    "{%0,%1,%2,%3}, {%4,%5,%6,%7}, {%8,%9}, {%0,%1,%2,%3};"
                    : "+f"(Sa[nt][0]), "+f"(Sa[nt][1]), "+f"(Sa[nt][2]), "+f"(Sa[nt][3])
                    : "r"(qfh[kc][0]), "r"(qfh[kc][1]), "r"(qfh[kc][2]), "r"(qfh[kc][3]),
                      "r"(bl0), "r"(bl1));
                asm volatile(
                    "mma.sync.aligned.m16n8k16.row.col.f32.bf16.bf16.f32 "
                    "{%0,%1,%2,%3}, {%4,%5,%6,%7}, {%8,%9}, {%0,%1,%2,%3};"
                    : "+f"(Sa[nt][0]), "+f"(Sa[nt][1]), "+f"(Sa[nt][2]), "+f"(Sa[nt][3])
                    : "r"(qfl[kc][0]), "r"(qfl[kc][1]), "r"(qfl[kc][2]), "r"(qfl[kc][3]),
                      "r"(bh0), "r"(bh1));
            }
        }

        if (j * 64 + 63 > wrow) {
            int s0 = wrow + lr, s1 = s0 + 8;
            #pragma unroll
            for (int nt = 0; nt < 8; nt++) {
                int t0 = j * 64 + nt * 8 + lc * 2;
                if (t0     > s0) Sa[nt][0] = -1e30f;
                if (t0 + 1 > s0) Sa[nt][1] = -1e30f;
                if (t0     > s1) Sa[nt][2] = -1e30f;
                if (t0 + 1 > s1) Sa[nt][3] = -1e30f;
            }
        }

        float mt0 = -1e30f, mt1 = -1e30f;
        #pragma unroll
        for (int nt = 0; nt < 8; nt++) {
            mt0 = fmaxf(mt0, fmaxf(Sa[nt][0], Sa[nt][1]));
            mt1 = fmaxf(mt1, fmaxf(Sa[nt][2], Sa[nt][3]));
        }
        mt0 = fmaxf(mt0, __shfl_xor_sync(0xffffffffu, mt0, 1));
        mt0 = fmaxf(mt0, __shfl_xor_sync(0xffffffffu, mt0, 2));
        mt1 = fmaxf(mt1, __shfl_xor_sync(0xffffffffu, mt1, 1));
        mt1 = fmaxf(mt1, __shfl_xor_sync(0xffffffffu, mt1, 2));
        float mn0 = fmaxf(m0, mt0), mn1 = fmaxf(m1, mt1);
        float a0 = __expf(m0 - mn0), a1 = __expf(m1 - mn1);
        m0 = mn0; m1 = mn1;

        float ps0 = 0.f, ps1 = 0.f;
        uint32_t pfh[4][4], pfl[4][4];
        #pragma unroll
        for (int nt = 0; nt < 8; nt++) {
            float p0 = __expf(Sa[nt][0] - m0);
            float p1 = __expf(Sa[nt][1] - m0);
            float p2 = __expf(Sa[nt][2] - m1);
            float p3 = __expf(Sa[nt][3] - m1);
            ps0 += p0 + p1;
            ps1 += p2 + p3;
            bf16 h0 = __float2bfloat16(p0), h1b = __float2bfloat16(p1);
            bf16 h2 = __float2bfloat16(p2), h3 = __float2bfloat16(p3);
            bf16 e0 = __float2bfloat16(p0 - __bfloat162float(h0));
            bf16 e1 = __float2bfloat16(p1 - __bfloat162float(h1b));
            bf16 e2 = __float2bfloat16(p2 - __bfloat162float(h2));
            bf16 e3 = __float2bfloat16(p3 - __bfloat162float(h3));
            __nv_bfloat162 ph01 = __nv_bfloat162(h0, h1b);
            __nv_bfloat162 ph23 = __nv_bfloat162(h2, h3);
            __nv_bfloat162 pl01 = __nv_bfloat162(e0, e1);
            __nv_bfloat162 pl23 = __nv_bfloat162(e2, e3);
            int kc = nt >> 1;
            if ((nt & 1) == 0) {
                pfh[kc][0] = *(uint32_t*)&ph01;
                pfh[kc][1] = *(uint32_t*)&ph23;
                pfl[kc][0] = *(uint32_t*)&pl01;
                pfl[kc][1] = *(uint32_t*)&pl23;
            } else {
                pfh[kc][2] = *(uint32_t*)&ph01;
                pfh[kc][3] = *(uint32_t*)&ph23;
                pfl[kc][2] = *(uint32_t*)&pl01;
                pfl[kc][3] = *(uint32_t*)&pl23;
            }
        }
        ps0 += __shfl_xor_sync(0xffffffffu, ps0, 1);
        ps0 += __shfl_xor_sync(0xffffffffu, ps0, 2);
        ps1 += __shfl_xor_sync(0xffffffffu, ps1, 1);
        ps1 += __shfl_xor_sync(0xffffffffu, ps1, 2);
        l0 = l0 * a0 + ps0;
        l1 = l1 * a1 + ps1;

        #pragma unroll
        for (int dt = 0; dt < 8; dt++) {
            Oa[dt][0] *= a0; Oa[dt][1] *= a0;
            Oa[dt][2] *= a1; Oa[dt][3] *= a1;
        }

        #pragma unroll
        for (int kc = 0; kc < 4; kc++) {
            #pragma unroll
            for (int dt = 0; dt < 8; dt++) {
                const bf16* vh = Vh + (dt * 8 + lr) * KSTR + kc * 16 + lc * 2;
                const bf16* vl = Vl + (dt * 8 + lr) * KSTR + kc * 16 + lc * 2;
                uint32_t vh0 = *(const uint32_t*)(vh);
                uint32_t vh1 = *(const uint32_t*)(vh + 8);
                uint32_t vl0 = *(const uint32_t*)(vl);
                uint32_t vl1 = *(const uint32_t*)(vl + 8);
                asm volatile(
                    "mma.sync.aligned.m16n8k16.row.col.f32.bf16.bf16.f32 "
                    "{%0,%1,%2,%3}, {%4,%5,%6,%7}, {%8,%9}, {%0,%1,%2,%3};"
                    : "+f"(Oa[dt][0]), "+f"(Oa[dt][1]), "+f"(Oa[dt][2]), "+f"(Oa[dt][3])
                    : "r"(pfh[kc][0]), "r"(pfh[kc][1]), "r"(pfh[kc][2]), "r"(pfh[kc][3]),
                      "r"(vh0), "r"(vh1));
                asm volatile(
                    "mma.sync.aligned.m16n8k16.row.col.f32.bf16.bf16.f32 "
                    "{%0,%1,%2,%3}, {%4,%5,%6,%7}, {%8,%9}, {%0,%1,%2,%3};"
                    : "+f"(Oa[dt][0]), "+f"(Oa[dt][1]), "+f"(Oa[dt][2]), "+f"(Oa[dt][3])
                    : "r"(pfh[kc][0]), "r"(pfh[kc][1]), "r"(pfh[kc][2]), "r"(pfh[kc][3]),
                      "r"(vl0), "r"(vl1));
                asm volatile(
                    "mma.sync.aligned.m16n8k16.row.col.f32.bf16.bf16.f32 "
                    "{%0,%1,%2,%3}, {%4,%5,%6,%7}, {%8,%9}, {%0,%1,%2,%3};"
                    : "+f"(Oa[dt][0]), "+f"(Oa[dt][1]), "+f"(Oa[dt][2]), "+f"(Oa[dt][3])
                    : "r"(pfl[kc][0]), "r"(pfl[kc][1]), "r"(pfl[kc][2]), "r"(pfl[kc][3]),
                      "r"(vh0), "r"(vh1));
            }
        }
    }

    float inv0 = 1.f / l0, inv1 = 1.f / l1;
    int s0 = wrow + lr;
    #pragma unroll
    for (int dt = 0; dt < 8; dt++) {
        int col = h * HD_ + dt * 8 + lc * 2;
        float o00 = Oa[dt][0] * inv0, o01 = Oa[dt][1] * inv0;
        float o10 = Oa[dt][2] * inv1, o11 = Oa[dt][3] * inv1;
        bf16 h00 = __float2bfloat16(o00), h01 = __float2bfloat16(o01);
        bf16 h10 = __float2bfloat16(o10), h11 = __float2bfloat16(o11);
        __nv_bfloat162 hi0 = __nv_bfloat162(h00, h01);
        __nv_bfloat162 hi1 = __nv_bfloat162(h10, h11);
        __nv_bfloat162 lo0 = __nv_bfloat162(__float2bfloat16(o00 - __bfloat162float(h00)),
                                            __float2bfloat16(o01 - __bfloat162float(h01)));
        __nv_bfloat162 lo1 = __nv_bfloat162(__float2bfloat16(o10 - __bfloat162float(h10)),
                                            __float2bfloat16(o11 - __bfloat162float(h11)));
        *(uint32_t*)(ohi + ((size_t)(b * S_ + s0)) * E_ + col)     = *(uint32_t*)&hi0;
        *(uint32_t*)(ohi + ((size_t)(b * S_ + s0 + 8)) * E_ + col) = *(uint32_t*)&hi1;
        *(uint32_t*)(olo + ((size_t)(b * S_ + s0)) * E_ + col)     = *(uint32_t*)&lo0;
        *(uint32_t*)(olo + ((size_t)(b * S_ + s0 + 8)) * E_ + col) = *(uint32_t*)&lo1;
    }
}

// ---------------- launch ---------------------------------------------------
extern "C" void kernel_launch(void* const* d_in, const int* in_sizes, int n_in,
                              void* d_out, int out_size)
{
    const float* x    = (const float*)d_in[0];
    const float* cosT = (const float*)d_in[2];
    const float* sinT = (const float*)d_in[3];
    const float* Wq   = (const float*)d_in[4];
    const float* Wk   = (const float*)d_in[5];
    const float* Wv   = (const float*)d_in[6];
    const float* Wo   = (const float*)d_in[7];

    float* out  = (float*)d_out;
    float* outK = out + (size_t)B_ * S_ * E_;
    float* outV = outK + (size_t)B_ * NKV_ * S_ * HD_;

    float *gqkv;
    bf16 *ahi, *alo, *wqkvhi, *wqkvlo, *wohi, *wolo;
    bf16 *qhi, *qlo, *khi, *klo, *vthi, *vtlo;
    cudaGetSymbolAddress((void**)&gqkv,   g_qkv);
    cudaGetSymbolAddress((void**)&ahi,    g_ahi);
    cudaGetSymbolAddress((void**)&alo,    g_alo);
    cudaGetSymbolAddress((void**)&wqkvhi, g_wqkvhi);
    cudaGetSymbolAddress((void**)&wqkvlo, g_wqkvlo);
    cudaGetSymbolAddress((void**)&wohi,   g_wohi);
    cudaGetSymbolAddress((void**)&wolo,   g_wolo);
    cudaGetSymbolAddress((void**)&qhi,    g_qhi);
    cudaGetSymbolAddress((void**)&qlo,    g_qlo);
    cudaGetSymbolAddress((void**)&khi,    g_khi);
    cudaGetSymbolAddress((void**)&klo,    g_klo);
    cudaGetSymbolAddress((void**)&vthi,   g_vthi);
    cudaGetSymbolAddress((void**)&vtlo,   g_vtlo);

    // weight conversions: Wq -> rows 0..2047, Wk -> 2048..2559, Wv -> 2560..3071
    {
        dim3 thr(32, 8);
        splitT_kernel<<<dim3(E_ / 32, E_ / 32), thr>>>(Wq, wqkvhi, wqkvlo, E_, E_);
        splitT_kernel<<<dim3((NKV_*HD_) / 32, E_ / 32), thr>>>(
            Wk, wqkvhi + (size_t)E_ * E_, wqkvlo + (size_t)E_ * E_, E_, NKV_*HD_);
        splitT_kernel<<<dim3((NKV_*HD_) / 32, E_ / 32), thr>>>(
            Wv, wqkvhi + (size_t)(E_ + NKV_*HD_) * E_, wqkvlo + (size_t)(E_ + NKV_*HD_) * E_,
            E_, NKV_*HD_);
        splitT_kernel<<<dim3(E_ / 32, E_ / 32), thr>>>(Wo, wohi, wolo, E_, E_);
    }
    // activation conversion
    {
        int n = MROWS * E_;
        split_kernel<<<(n + 255) / 256, 256>>>(x, ahi, alo, n);
    }

    // fused QKV projection
    cudaFuncSetAttribute(gemm_pipe, cudaFuncAttributeMaxDynamicSharedMemorySize, GEMM_SMEM);
    gemm_pipe<<<dim3(NQKV / 128, MROWS / 128), 256, GEMM_SMEM>>>(
        ahi, alo, wqkvhi, wqkvlo, gqkv, MROWS, NQKV, E_);

    // rope + transposes + splits
    {
        int tq = B_ * S_ * NH_ * 32;
        rope_q_kernel<<<(tq + 255) / 256, 256>>>(gqkv, cosT, sinT, qhi, qlo);
        int tk = B_ * S_ * NKV_ * 32;
        rope_k_kernel<<<(tk + 255) / 256, 256>>>(gqkv, cosT, sinT, outK, khi, klo);
        int tv = B_ * S_ * 128;
        copy_v_kernel<<<(tv + 255) / 256, 256>>>(gqkv, outV);
        vT_split_kernel<<<dim3(S_ / 32, B_ * NKV_), 256>>>(gqkv, vthi, vtlo);
    }

    // flash attention -> writes ahi/alo directly
    {
        dim3 grid(S_ / 128, NH_, B_);
        flash_mma<<<grid, 256>>>(qhi, qlo, khi, klo, vthi, vtlo, ahi, alo);
    }

    // output projection
    gemm_pipe<<<dim3(E_ / 128, MROWS / 128), 256, GEMM_SMEM>>>(
        ahi, alo, wohi, wolo, out, MROWS, E_, E_);
}